// round 2
// baseline (speedup 1.0000x reference)
#include <cuda_runtime.h>
#include <math.h>

#define BATCH 256
#define NN    1024
#define PP    128
#define DIN   784
#define COUT  10

#define TWO_PI_F 6.283185307179586f
#define DT       0.03125f            /* T/N_STEPS = 0.5/16, exact in fp32 */
#define BETA_N   (2.0f/1024.0f)
#define A_ANC    0.08f
#define OME      (TWO_PI_F*200.0f)

/* ---- device scratch (static globals; no allocation allowed) ---- */
__device__ float g_xc[PP*NN];     /* cos(xi) [p][n] */
__device__ float g_xs[PP*NN];     /* sin(xi) [p][n] */
__device__ float g_phi[BATCH*NN];   /* base state */
__device__ float g_phie[BATCH*NN];  /* eval point */
__device__ float g_acc[BATCH*NN];   /* RK4 accumulator */
__device__ float g_m[3][BATCH*PP];  /* rotating overlap buffers */

/* ---- shared layout ---- */
#define SW_STRIDE 132                /* w tile [32][132] */
#define SX_STRIDE 68                 /* xc/xs tiles [128][68] */
#define SC_STRIDE 66                 /* c/s tiles [32][66] */
#define SW_FLOATS (32*SW_STRIDE)     /* 4224 */
#define SX_FLOATS (128*SX_STRIDE)    /* 8704 */
#define SC_FLOATS (32*SC_STRIDE)     /* 2112 */
#define SMEM_FLOATS (SW_FLOATS + 2*SX_FLOATS + 2*SC_FLOATS)
#define SMEM_BYTES  (SMEM_FLOATS*4)  /* 103424 bytes */

/* ================= init: cos/sin of xi + zero first two m buffers ======= */
__global__ void k_init(const float* __restrict__ xi) {
    int i = blockIdx.x*256 + threadIdx.x;
    if (i < PP*NN) {
        float v = xi[i];
        g_xc[i] = cosf(v);
        g_xs[i] = sinf(v);
    }
    if (i < BATCH*PP) { g_m[0][i] = 0.f; g_m[1][i] = 0.f; }
}

/* load xc/xs tiles [128 p][64 n] for column chunk n0 into shared */
__device__ __forceinline__ void load_xtiles(float* sXC, float* sXS, int n0) {
    for (int i = threadIdx.x; i < 128*16; i += 256) {
        int p = i >> 4, q = (i & 15) << 2;
        float4 a = *(const float4*)&g_xc[p*NN + n0 + q];
        *(float4*)&sXC[p*SX_STRIDE + q] = a;
        float4 b = *(const float4*)&g_xs[p*NN + n0 + q];
        *(float4*)&sXS[p*SX_STRIDE + q] = b;
    }
}

/* partial m over this CTA's 64-col chunk, atomically added into mbuf.
   thread layout: row = tid>>3 (32 rows), pg = tid&7; 16 patterns p = pg + 8i. */
__device__ __forceinline__ void m_tail(const float* sC, const float* sS,
                                       const float* sXC, const float* sXS,
                                       float* mbuf, int r0) {
    int row = threadIdx.x >> 3;
    int pg  = threadIdx.x & 7;
    float acc[16];
#pragma unroll
    for (int i = 0; i < 16; i++) acc[i] = 0.f;
    const float* cRow = sC + row*SC_STRIDE;
    const float* sRow = sS + row*SC_STRIDE;
#pragma unroll 2
    for (int n = 0; n < 64; n++) {
        float c = cRow[n], s = sRow[n];
#pragma unroll
        for (int i = 0; i < 16; i++) {
            int p = pg + (i << 3);
            acc[i] += c*sXC[p*SX_STRIDE + n] + s*sXS[p*SX_STRIDE + n];
        }
    }
#pragma unroll
    for (int i = 0; i < 16; i++) {
        int p = pg + (i << 3);
        atomicAdd(&mbuf[(r0+row)*PP + p], acc[i]);
    }
}

/* ================= encoder: phi0 = 2pi*sigmoid(x @ Wenc^T + b), + m0 ==== */
__global__ void k_encoder(const float* __restrict__ x,
                          const float* __restrict__ Wenc,
                          const float* __restrict__ benc) {
    extern __shared__ float sm[];
    float* sA  = sm;                 /* [32][17] staging, aliases sW region */
    float* sB  = sm + 32*17;         /* [64][17] */
    float* sXC = sm + SW_FLOATS;
    float* sXS = sXC + SX_FLOATS;
    float* sC  = sXS + SX_FLOATS;
    float* sS  = sC + SC_FLOATS;

    int n0 = blockIdx.x*64, r0 = blockIdx.y*32;
    int tid = threadIdx.x;
    int row = tid >> 3, ng = tid & 7, nb = ng*8;

    float acc[8];
#pragma unroll
    for (int i = 0; i < 8; i++) acc[i] = 0.f;

    for (int d0 = 0; d0 < DIN; d0 += 16) {
        for (int i = tid; i < 512; i += 256) {
            int r = i >> 4, j = i & 15;
            sA[r*17 + j] = x[(r0+r)*DIN + d0 + j];
        }
        for (int i = tid; i < 1024; i += 256) {
            int r = i >> 4, j = i & 15;
            sB[r*17 + j] = Wenc[(n0+r)*DIN + d0 + j];
        }
        __syncthreads();
#pragma unroll
        for (int j = 0; j < 16; j++) {
            float xa = sA[row*17 + j];
#pragma unroll
            for (int i = 0; i < 8; i++) acc[i] += xa * sB[(nb+i)*17 + j];
        }
        __syncthreads();
    }

    load_xtiles(sXC, sXS, n0);

#pragma unroll
    for (int i = 0; i < 8; i++) {
        float z  = acc[i] + benc[n0 + nb + i];
        float p0 = TWO_PI_F / (1.0f + expf(-z));
        int gi = (r0+row)*NN + n0 + nb + i;
        g_phi[gi]  = p0;
        g_phie[gi] = p0;
        float ss, cc;
        __sincosf(p0, &ss, &cc);
        sC[row*SC_STRIDE + nb + i] = cc;
        sS[row*SC_STRIDE + nb + i] = ss;
    }
    __syncthreads();
    m_tail(sC, sS, sXC, sXS, g_m[0], r0);
}

/* ================= fused per-eval kernel ================================ */
/* sub: RK4 substage 0..3; tE: eval time; cNext: coeff for next eval point
   bufR/bufW/bufZ: m buffer rotation; doTail: compute next m partials       */
__global__ void k_F(int sub, float tE, float cNext,
                    int bufR, int bufW, int bufZ, int doTail) {
    extern __shared__ float sm[];
    float* sW  = sm;
    float* sXC = sm + SW_FLOATS;
    float* sXS = sXC + SX_FLOATS;
    float* sC  = sXS + SX_FLOATS;
    float* sS  = sC + SC_FLOATS;

    int n0 = blockIdx.x*64, r0 = blockIdx.y*32;
    int tid = threadIdx.x;
    int row = tid >> 3, l8 = tid & 7;

    /* zero this CTA's slice of the buffer used two evals ahead */
    {
        int cta = blockIdx.y*16 + blockIdx.x;          /* 0..127 */
        g_m[bufZ][cta*256 + tid] = 0.f;
    }

    /* ---- P0: softmax over 128 patterns for our 32 rows ---- */
    {
        const float* mrow = &g_m[bufR][(r0+row)*PP];
        float a[16];
        float mx = -1e30f;
#pragma unroll
        for (int j = 0; j < 16; j++) {
            a[j] = mrow[l8 + (j << 3)] * BETA_N;
            mx = fmaxf(mx, a[j]);
        }
#pragma unroll
        for (int w = 1; w < 8; w <<= 1)
            mx = fmaxf(mx, __shfl_xor_sync(0xffffffffu, mx, w));
        float ssum = 0.f;
#pragma unroll
        for (int j = 0; j < 16; j++) { a[j] = expf(a[j] - mx); ssum += a[j]; }
#pragma unroll
        for (int w = 1; w < 8; w <<= 1)
            ssum += __shfl_xor_sync(0xffffffffu, ssum, w);
        float inv = 1.0f / ssum;
#pragma unroll
        for (int j = 0; j < 16; j++)
            sW[row*SW_STRIDE + l8 + (j << 3)] = a[j] * inv;
    }

    load_xtiles(sXC, sXS, n0);
    __syncthreads();

    /* ---- P2: coupling GEMM  wc = w@xc, ws = w@xs  (K = 128) ---- */
    int nb = l8 * 8;
    float wc[8], ws[8];
#pragma unroll
    for (int i = 0; i < 8; i++) { wc[i] = 0.f; ws[i] = 0.f; }
    {
        const float* wRow = &sW[row*SW_STRIDE];
#pragma unroll 4
        for (int p = 0; p < PP; p++) {
            float wv = wRow[p];
            const float* xcp = &sXC[p*SX_STRIDE + nb];
            const float* xsp = &sXS[p*SX_STRIDE + nb];
            float4 c0 = *(const float4*)&xcp[0];
            float4 c1 = *(const float4*)&xcp[4];
            float4 s0 = *(const float4*)&xsp[0];
            float4 s1 = *(const float4*)&xsp[4];
            wc[0] += wv*c0.x; wc[1] += wv*c0.y; wc[2] += wv*c0.z; wc[3] += wv*c0.w;
            wc[4] += wv*c1.x; wc[5] += wv*c1.y; wc[6] += wv*c1.z; wc[7] += wv*c1.w;
            ws[0] += wv*s0.x; ws[1] += wv*s0.y; ws[2] += wv*s0.z; ws[3] += wv*s0.w;
            ws[4] += wv*s1.x; ws[5] += wv*s1.y; ws[6] += wv*s1.z; ws[7] += wv*s1.w;
        }
    }

    /* ---- elementwise: k = sin*wc - cos*ws + A*sin(w t - phi); RK4 ---- */
    int gbase = (r0+row)*NN + n0 + nb;
    float kv[8];
#pragma unroll
    for (int j = 0; j < 8; j++) {
        float pe = g_phie[gbase + j];
        float se, ce;
        __sincosf(pe, &se, &ce);
        float anc = sinf(OME*tE - pe);      /* accurate sinf: large argument */
        kv[j] = (se*wc[j] - ce*ws[j]) + A_ANC*anc;
    }

    float phiN[8];
    if (sub == 0) {
#pragma unroll
        for (int j = 0; j < 8; j++) {
            g_acc[gbase + j] = kv[j];
            phiN[j] = g_phi[gbase + j] + cNext*kv[j];
        }
    } else if (sub == 3) {
#pragma unroll
        for (int j = 0; j < 8; j++) {
            float pn = g_phi[gbase + j]
                     + (DT/6.0f) * (g_acc[gbase + j] + kv[j]);
            g_phi[gbase + j] = pn;
            phiN[j] = pn;
        }
    } else {
#pragma unroll
        for (int j = 0; j < 8; j++) {
            g_acc[gbase + j] += 2.0f*kv[j];
            phiN[j] = g_phi[gbase + j] + cNext*kv[j];
        }
    }
#pragma unroll
    for (int j = 0; j < 8; j++) g_phie[gbase + j] = phiN[j];

    /* ---- tail: features of next eval point -> partial m ---- */
    if (doTail) {
#pragma unroll
        for (int j = 0; j < 8; j++) {
            float sn, cn;
            __sincosf(phiN[j], &sn, &cn);
            sC[row*SC_STRIDE + nb + j] = cn;
            sS[row*SC_STRIDE + nb + j] = sn;
        }
        __syncthreads();
        m_tail(sC, sS, sXC, sXS, g_m[bufW], r0);
    }
}

/* ================= readout: [cos(phi), sin(phi)] @ Wout^T + b =========== */
__global__ void k_readout(const float* __restrict__ Wout,
                          const float* __restrict__ bout,
                          float* __restrict__ out) {
    __shared__ float red[256];
    int b = blockIdx.x, tid = threadIdx.x;
    float acc[COUT];
#pragma unroll
    for (int c = 0; c < COUT; c++) acc[c] = 0.f;

#pragma unroll
    for (int it = 0; it < 4; it++) {
        int n = tid + it*256;
        float phi = g_phi[b*NN + n];
        float s, c;
        sincosf(phi, &s, &c);     /* accurate: feeds output directly */
#pragma unroll
        for (int cls = 0; cls < COUT; cls++)
            acc[cls] += c*Wout[cls*(2*NN) + n] + s*Wout[cls*(2*NN) + NN + n];
    }
    for (int cls = 0; cls < COUT; cls++) {
        red[tid] = acc[cls];
        __syncthreads();
        for (int off = 128; off > 0; off >>= 1) {
            if (tid < off) red[tid] += red[tid + off];
            __syncthreads();
        }
        if (tid == 0) out[b*COUT + cls] = red[0] + bout[cls];
        __syncthreads();
    }
}

/* ================= host ================================================= */
extern "C" void kernel_launch(void* const* d_in, const int* in_sizes, int n_in,
                              void* d_out, int out_size) {
    (void)in_sizes; (void)n_in; (void)out_size;
    const float* x    = (const float*)d_in[0];
    const float* Wenc = (const float*)d_in[1];
    const float* benc = (const float*)d_in[2];
    const float* xi   = (const float*)d_in[3];
    const float* Wout = (const float*)d_in[4];
    const float* bout = (const float*)d_in[5];
    float* out = (float*)d_out;

    cudaFuncSetAttribute(k_encoder, cudaFuncAttributeMaxDynamicSharedMemorySize, SMEM_BYTES);
    cudaFuncSetAttribute(k_F,       cudaFuncAttributeMaxDynamicSharedMemorySize, SMEM_BYTES);

    k_init<<<512, 256>>>(xi);

    dim3 grid(16, 8);
    k_encoder<<<grid, 256, SMEM_BYTES>>>(x, Wenc, benc);

    for (int e = 0; e < 64; e++) {
        int step = e >> 2, sub = e & 3;
        float t0 = (float)step * DT;
        float tE = (sub == 0) ? t0 : ((sub == 3) ? t0 + DT : t0 + 0.5f*DT);
        float cNext = (sub == 2) ? DT : 0.5f*DT;   /* coeff toward next eval */
        int bufR = e % 3, bufW = (e + 1) % 3, bufZ = (e + 2) % 3;
        int doTail = (e < 63) ? 1 : 0;
        k_F<<<grid, 256, SMEM_BYTES>>>(sub, tE, cNext, bufR, bufW, bufZ, doTail);
    }

    k_readout<<<BATCH, 256>>>(Wout, bout, out);
}

// round 3
// speedup vs baseline: 1.0035x; 1.0035x over previous
#include <cuda_runtime.h>
#include <math.h>

#define BATCH 256
#define NN    1024
#define PP    128
#define DIN   784
#define COUT  10

#define TWO_PI_F 6.283185307179586f
#define DT       0.03125f            /* T/N_STEPS = 0.5/16, exact in fp32 */
#define BETA_N   (2.0f/1024.0f)
#define A_ANC    0.08f
#define OME      (TWO_PI_F*200.0f)

/* ---- device scratch (static globals; no allocation allowed) ---- */
__device__ float g_xc[PP*NN];     /* cos(xi) [p][n] */
__device__ float g_xs[PP*NN];     /* sin(xi) [p][n] */
__device__ float g_phi[BATCH*NN];   /* base state */
__device__ float g_phie[BATCH*NN];  /* eval point */
__device__ float g_acc[BATCH*NN];   /* RK4 accumulator */
__device__ float g_m[3][BATCH*PP];  /* rotating overlap buffers */

/* ---- shared layout ---- */
#define SW_STRIDE 132                /* w tile [32][132] */
#define SX_STRIDE 68                 /* xc/xs tiles [128][68] */
#define SC_STRIDE 66                 /* c/s tiles [32][66] */
#define SW_FLOATS (32*SW_STRIDE)     /* 4224 */
#define SX_FLOATS (128*SX_STRIDE)    /* 8704 */
#define SC_FLOATS (32*SC_STRIDE)     /* 2112 */
#define SMEM_FLOATS (SW_FLOATS + 2*SX_FLOATS + 2*SC_FLOATS)
#define SMEM_BYTES  (SMEM_FLOATS*4)  /* 103424 bytes */

/* ================= init: cos/sin of xi + zero first two m buffers ======= */
__global__ void k_init(const float* __restrict__ xi) {
    int i = blockIdx.x*256 + threadIdx.x;
    if (i < PP*NN) {
        float v = xi[i];
        g_xc[i] = cosf(v);
        g_xs[i] = sinf(v);
    }
    if (i < BATCH*PP) { g_m[0][i] = 0.f; g_m[1][i] = 0.f; }
}

/* load xc/xs tiles [128 p][64 n] for column chunk n0 into shared */
__device__ __forceinline__ void load_xtiles(float* sXC, float* sXS, int n0) {
    for (int i = threadIdx.x; i < 128*16; i += 256) {
        int p = i >> 4, q = (i & 15) << 2;
        float4 a = *(const float4*)&g_xc[p*NN + n0 + q];
        *(float4*)&sXC[p*SX_STRIDE + q] = a;
        float4 b = *(const float4*)&g_xs[p*NN + n0 + q];
        *(float4*)&sXS[p*SX_STRIDE + q] = b;
    }
}

/* partial m over this CTA's 64-col chunk, atomically added into mbuf.
   thread layout: row = tid>>3 (32 rows), pg = tid&7; 16 patterns p = pg + 8i. */
__device__ __forceinline__ void m_tail(const float* sC, const float* sS,
                                       const float* sXC, const float* sXS,
                                       float* mbuf, int r0) {
    int row = threadIdx.x >> 3;
    int pg  = threadIdx.x & 7;
    float acc[16];
#pragma unroll
    for (int i = 0; i < 16; i++) acc[i] = 0.f;
    const float* cRow = sC + row*SC_STRIDE;
    const float* sRow = sS + row*SC_STRIDE;
#pragma unroll 2
    for (int n = 0; n < 64; n++) {
        float c = cRow[n], s = sRow[n];
#pragma unroll
        for (int i = 0; i < 16; i++) {
            int p = pg + (i << 3);
            acc[i] += c*sXC[p*SX_STRIDE + n] + s*sXS[p*SX_STRIDE + n];
        }
    }
#pragma unroll
    for (int i = 0; i < 16; i++) {
        int p = pg + (i << 3);
        atomicAdd(&mbuf[(r0+row)*PP + p], acc[i]);
    }
}

/* ================= encoder: phi0 = 2pi*sigmoid(x @ Wenc^T + b), + m0 ==== */
__global__ void k_encoder(const float* __restrict__ x,
                          const float* __restrict__ Wenc,
                          const float* __restrict__ benc) {
    extern __shared__ float sm[];
    float* sA  = sm;                 /* [32][17] staging, aliases sW region */
    float* sB  = sm + 32*17;         /* [64][17] */
    float* sXC = sm + SW_FLOATS;
    float* sXS = sXC + SX_FLOATS;
    float* sC  = sXS + SX_FLOATS;
    float* sS  = sC + SC_FLOATS;

    int n0 = blockIdx.x*64, r0 = blockIdx.y*32;
    int tid = threadIdx.x;
    int row = tid >> 3, ng = tid & 7, nb = ng*8;

    float acc[8];
#pragma unroll
    for (int i = 0; i < 8; i++) acc[i] = 0.f;

    for (int d0 = 0; d0 < DIN; d0 += 16) {
        for (int i = tid; i < 512; i += 256) {
            int r = i >> 4, j = i & 15;
            sA[r*17 + j] = x[(r0+r)*DIN + d0 + j];
        }
        for (int i = tid; i < 1024; i += 256) {
            int r = i >> 4, j = i & 15;
            sB[r*17 + j] = Wenc[(n0+r)*DIN + d0 + j];
        }
        __syncthreads();
#pragma unroll
        for (int j = 0; j < 16; j++) {
            float xa = sA[row*17 + j];
#pragma unroll
            for (int i = 0; i < 8; i++) acc[i] += xa * sB[(nb+i)*17 + j];
        }
        __syncthreads();
    }

    load_xtiles(sXC, sXS, n0);

#pragma unroll
    for (int i = 0; i < 8; i++) {
        float z  = acc[i] + benc[n0 + nb + i];
        float p0 = TWO_PI_F / (1.0f + expf(-z));
        int gi = (r0+row)*NN + n0 + nb + i;
        g_phi[gi]  = p0;
        g_phie[gi] = p0;
        float ss, cc;
        __sincosf(p0, &ss, &cc);
        sC[row*SC_STRIDE + nb + i] = cc;
        sS[row*SC_STRIDE + nb + i] = ss;
    }
    __syncthreads();
    m_tail(sC, sS, sXC, sXS, g_m[0], r0);
}

/* ================= fused per-eval kernel ================================ */
/* sub: RK4 substage 0..3; tE: eval time; cNext: coeff for next eval point
   bufR/bufW/bufZ: m buffer rotation; doTail: compute next m partials       */
__global__ void k_F(int sub, float tE, float cNext,
                    int bufR, int bufW, int bufZ, int doTail) {
    extern __shared__ float sm[];
    float* sW  = sm;
    float* sXC = sm + SW_FLOATS;
    float* sXS = sXC + SX_FLOATS;
    float* sC  = sXS + SX_FLOATS;
    float* sS  = sC + SC_FLOATS;

    int n0 = blockIdx.x*64, r0 = blockIdx.y*32;
    int tid = threadIdx.x;
    int row = tid >> 3, l8 = tid & 7;

    /* zero this CTA's slice of the buffer used two evals ahead */
    {
        int cta = blockIdx.y*16 + blockIdx.x;          /* 0..127 */
        g_m[bufZ][cta*256 + tid] = 0.f;
    }

    /* ---- P0: softmax over 128 patterns for our 32 rows ---- */
    {
        const float* mrow = &g_m[bufR][(r0+row)*PP];
        float a[16];
        float mx = -1e30f;
#pragma unroll
        for (int j = 0; j < 16; j++) {
            a[j] = mrow[l8 + (j << 3)] * BETA_N;
            mx = fmaxf(mx, a[j]);
        }
#pragma unroll
        for (int w = 1; w < 8; w <<= 1)
            mx = fmaxf(mx, __shfl_xor_sync(0xffffffffu, mx, w));
        float ssum = 0.f;
#pragma unroll
        for (int j = 0; j < 16; j++) { a[j] = expf(a[j] - mx); ssum += a[j]; }
#pragma unroll
        for (int w = 1; w < 8; w <<= 1)
            ssum += __shfl_xor_sync(0xffffffffu, ssum, w);
        float inv = 1.0f / ssum;
#pragma unroll
        for (int j = 0; j < 16; j++)
            sW[row*SW_STRIDE + l8 + (j << 3)] = a[j] * inv;
    }

    load_xtiles(sXC, sXS, n0);
    __syncthreads();

    /* ---- P2: coupling GEMM  wc = w@xc, ws = w@xs  (K = 128) ---- */
    int nb = l8 * 8;
    float wc[8], ws[8];
#pragma unroll
    for (int i = 0; i < 8; i++) { wc[i] = 0.f; ws[i] = 0.f; }
    {
        const float* wRow = &sW[row*SW_STRIDE];
#pragma unroll 4
        for (int p = 0; p < PP; p++) {
            float wv = wRow[p];
            const float* xcp = &sXC[p*SX_STRIDE + nb];
            const float* xsp = &sXS[p*SX_STRIDE + nb];
            float4 c0 = *(const float4*)&xcp[0];
            float4 c1 = *(const float4*)&xcp[4];
            float4 s0 = *(const float4*)&xsp[0];
            float4 s1 = *(const float4*)&xsp[4];
            wc[0] += wv*c0.x; wc[1] += wv*c0.y; wc[2] += wv*c0.z; wc[3] += wv*c0.w;
            wc[4] += wv*c1.x; wc[5] += wv*c1.y; wc[6] += wv*c1.z; wc[7] += wv*c1.w;
            ws[0] += wv*s0.x; ws[1] += wv*s0.y; ws[2] += wv*s0.z; ws[3] += wv*s0.w;
            ws[4] += wv*s1.x; ws[5] += wv*s1.y; ws[6] += wv*s1.z; ws[7] += wv*s1.w;
        }
    }

    /* ---- elementwise: k = sin*wc - cos*ws + A*sin(w t - phi); RK4 ---- */
    int gbase = (r0+row)*NN + n0 + nb;
    float kv[8];
#pragma unroll
    for (int j = 0; j < 8; j++) {
        float pe = g_phie[gbase + j];
        float se, ce;
        __sincosf(pe, &se, &ce);
        float anc = sinf(OME*tE - pe);      /* accurate sinf: large argument */
        kv[j] = (se*wc[j] - ce*ws[j]) + A_ANC*anc;
    }

    float phiN[8];
    if (sub == 0) {
#pragma unroll
        for (int j = 0; j < 8; j++) {
            g_acc[gbase + j] = kv[j];
            phiN[j] = g_phi[gbase + j] + cNext*kv[j];
        }
    } else if (sub == 3) {
#pragma unroll
        for (int j = 0; j < 8; j++) {
            float pn = g_phi[gbase + j]
                     + (DT/6.0f) * (g_acc[gbase + j] + kv[j]);
            g_phi[gbase + j] = pn;
            phiN[j] = pn;
        }
    } else {
#pragma unroll
        for (int j = 0; j < 8; j++) {
            g_acc[gbase + j] += 2.0f*kv[j];
            phiN[j] = g_phi[gbase + j] + cNext*kv[j];
        }
    }
#pragma unroll
    for (int j = 0; j < 8; j++) g_phie[gbase + j] = phiN[j];

    /* ---- tail: features of next eval point -> partial m ---- */
    if (doTail) {
#pragma unroll
        for (int j = 0; j < 8; j++) {
            float sn, cn;
            __sincosf(phiN[j], &sn, &cn);
            sC[row*SC_STRIDE + nb + j] = cn;
            sS[row*SC_STRIDE + nb + j] = sn;
        }
        __syncthreads();
        m_tail(sC, sS, sXC, sXS, g_m[bufW], r0);
    }
}

/* ================= readout: [cos(phi), sin(phi)] @ Wout^T + b =========== */
__global__ void k_readout(const float* __restrict__ Wout,
                          const float* __restrict__ bout,
                          float* __restrict__ out) {
    __shared__ float red[256];
    int b = blockIdx.x, tid = threadIdx.x;
    float acc[COUT];
#pragma unroll
    for (int c = 0; c < COUT; c++) acc[c] = 0.f;

#pragma unroll
    for (int it = 0; it < 4; it++) {
        int n = tid + it*256;
        float phi = g_phi[b*NN + n];
        float s, c;
        sincosf(phi, &s, &c);     /* accurate: feeds output directly */
#pragma unroll
        for (int cls = 0; cls < COUT; cls++)
            acc[cls] += c*Wout[cls*(2*NN) + n] + s*Wout[cls*(2*NN) + NN + n];
    }
    for (int cls = 0; cls < COUT; cls++) {
        red[tid] = acc[cls];
        __syncthreads();
        for (int off = 128; off > 0; off >>= 1) {
            if (tid < off) red[tid] += red[tid + off];
            __syncthreads();
        }
        if (tid == 0) out[b*COUT + cls] = red[0] + bout[cls];
        __syncthreads();
    }
}

/* ================= host ================================================= */
extern "C" void kernel_launch(void* const* d_in, const int* in_sizes, int n_in,
                              void* d_out, int out_size) {
    (void)in_sizes; (void)n_in; (void)out_size;
    const float* x    = (const float*)d_in[0];
    const float* Wenc = (const float*)d_in[1];
    const float* benc = (const float*)d_in[2];
    const float* xi   = (const float*)d_in[3];
    const float* Wout = (const float*)d_in[4];
    const float* bout = (const float*)d_in[5];
    float* out = (float*)d_out;

    cudaFuncSetAttribute(k_encoder, cudaFuncAttributeMaxDynamicSharedMemorySize, SMEM_BYTES);
    cudaFuncSetAttribute(k_F,       cudaFuncAttributeMaxDynamicSharedMemorySize, SMEM_BYTES);

    k_init<<<512, 256>>>(xi);

    dim3 grid(16, 8);
    k_encoder<<<grid, 256, SMEM_BYTES>>>(x, Wenc, benc);

    for (int e = 0; e < 64; e++) {
        int step = e >> 2, sub = e & 3;
        float t0 = (float)step * DT;
        float tE = (sub == 0) ? t0 : ((sub == 3) ? t0 + DT : t0 + 0.5f*DT);
        float cNext = (sub == 2) ? DT : 0.5f*DT;   /* coeff toward next eval */
        int bufR = e % 3, bufW = (e + 1) % 3, bufZ = (e + 2) % 3;
        int doTail = (e < 63) ? 1 : 0;
        k_F<<<grid, 256, SMEM_BYTES>>>(sub, tE, cNext, bufR, bufW, bufZ, doTail);
    }

    k_readout<<<BATCH, 256>>>(Wout, bout, out);
}

// round 4
// speedup vs baseline: 1.7621x; 1.7559x over previous
#include <cuda_runtime.h>
#include <math.h>

#define BATCH 256
#define NN    1024
#define PP    128
#define DIN   784
#define COUT  10

#define TWO_PI_F 6.283185307179586f
#define DT       0.03125f            /* T/N_STEPS = 0.5/16, exact in fp32 */
#define BETA_N   (2.0f/1024.0f)
#define A_ANC    0.08f
#define OME      (TWO_PI_F*200.0f)

/* ---- device scratch (static globals; no allocation allowed) ---- */
__device__ float g_xc[PP*NN];     /* cos(xi) [p][n] */
__device__ float g_xs[PP*NN];     /* sin(xi) [p][n] */
__device__ float g_phi[BATCH*NN];   /* base state */
__device__ float g_phie[BATCH*NN];  /* eval point */
__device__ float g_acc[BATCH*NN];   /* RK4 accumulator */
__device__ float g_m[3][BATCH*PP];  /* rotating overlap buffers */

/* ---- shared layout ---- */
#define SW_STRIDE 132                /* w tile [32][132] */
#define SX_STRIDE 68                 /* xc/xs tiles [128][68] */
#define SC_STRIDE 68                 /* c/s tiles [32][68] (mult of 4 for f4) */
#define SR_STRIDE 36                 /* reduction buffer [128][36] */
#define SW_FLOATS (32*SW_STRIDE)     /* 4224 */
#define SX_FLOATS (128*SX_STRIDE)    /* 8704 */
#define SC_FLOATS (32*SC_STRIDE)     /* 2176 */
#define SR_FLOATS (128*SR_STRIDE)    /* 4608 */
#define SMEM_FLOATS (SW_FLOATS + 2*SX_FLOATS + 2*SC_FLOATS + SR_FLOATS)
#define SMEM_BYTES  (SMEM_FLOATS*4)  /* 122368 bytes */

/* ================= init: cos/sin of xi + zero first two m buffers ======= */
__global__ void k_init(const float* __restrict__ xi) {
    int i = blockIdx.x*256 + threadIdx.x;
    if (i < PP*NN) {
        float v = xi[i];
        g_xc[i] = cosf(v);
        g_xs[i] = sinf(v);
    }
    if (i < BATCH*PP) { g_m[0][i] = 0.f; g_m[1][i] = 0.f; }
}

/* load xc/xs tiles [128 p][64 n] for column chunk n0 into shared */
__device__ __forceinline__ void load_xtiles(float* sXC, float* sXS, int n0) {
    for (int i = threadIdx.x; i < 128*16; i += 256) {
        int p = i >> 4, q = (i & 15) << 2;
        float4 a = *(const float4*)&g_xc[p*NN + n0 + q];
        *(float4*)&sXC[p*SX_STRIDE + q] = a;
        float4 b = *(const float4*)&g_xs[p*NN + n0 + q];
        *(float4*)&sXS[p*SX_STRIDE + q] = b;
    }
}

/* partial m over this CTA's 64-col chunk, atomically added into mbuf.
   Register-blocked 4 rows x 4 patterns; float4 over n.
   rb = tid>>5 (8 blocks of 4 rows), pb = tid&31; patterns p = pb + 32j.
   xc lane stride = 68 floats = 272B == 16 mod 128 -> conflict-free. */
__device__ __forceinline__ void m_tail(const float* sC, const float* sS,
                                       const float* sXC, const float* sXS,
                                       float* mbuf, int r0) {
    int rb = threadIdx.x >> 5;
    int pb = threadIdx.x & 31;
    float acc[16];
#pragma unroll
    for (int i = 0; i < 16; i++) acc[i] = 0.f;
    const float* cB = sC + (rb*4)*SC_STRIDE;
    const float* sB = sS + (rb*4)*SC_STRIDE;
#pragma unroll 4
    for (int n = 0; n < 64; n += 4) {
        float4 cr[4], sr[4];
#pragma unroll
        for (int r = 0; r < 4; r++) {
            cr[r] = *(const float4*)&cB[r*SC_STRIDE + n];
            sr[r] = *(const float4*)&sB[r*SC_STRIDE + n];
        }
#pragma unroll
        for (int j = 0; j < 4; j++) {
            int p = pb + (j << 5);
            float4 xc4 = *(const float4*)&sXC[p*SX_STRIDE + n];
            float4 xs4 = *(const float4*)&sXS[p*SX_STRIDE + n];
#pragma unroll
            for (int r = 0; r < 4; r++) {
                float t = acc[j*4 + r];
                t = fmaf(cr[r].x, xc4.x, t); t = fmaf(sr[r].x, xs4.x, t);
                t = fmaf(cr[r].y, xc4.y, t); t = fmaf(sr[r].y, xs4.y, t);
                t = fmaf(cr[r].z, xc4.z, t); t = fmaf(sr[r].z, xs4.z, t);
                t = fmaf(cr[r].w, xc4.w, t); t = fmaf(sr[r].w, xs4.w, t);
                acc[j*4 + r] = t;
            }
        }
    }
#pragma unroll
    for (int j = 0; j < 4; j++)
#pragma unroll
        for (int r = 0; r < 4; r++)
            atomicAdd(&mbuf[(r0 + rb*4 + r)*PP + pb + (j << 5)], acc[j*4 + r]);
}

/* ================= encoder: phi0 = 2pi*sigmoid(x @ Wenc^T + b), + m0 ==== */
__global__ void __launch_bounds__(256, 1)
k_encoder(const float* __restrict__ x,
          const float* __restrict__ Wenc,
          const float* __restrict__ benc) {
    extern __shared__ float sm[];
    float* sA  = sm;                 /* [32][17] staging, aliases sW region */
    float* sB  = sm + 32*17;         /* [64][17] */
    float* sXC = sm + SW_FLOATS;
    float* sXS = sXC + SX_FLOATS;
    float* sC  = sXS + SX_FLOATS;
    float* sS  = sC + SC_FLOATS;

    int n0 = blockIdx.x*64, r0 = blockIdx.y*32;
    int tid = threadIdx.x;
    int row = tid >> 3, ng = tid & 7, nb = ng*8;

    float acc[8];
#pragma unroll
    for (int i = 0; i < 8; i++) acc[i] = 0.f;

    for (int d0 = 0; d0 < DIN; d0 += 16) {
        for (int i = tid; i < 512; i += 256) {
            int r = i >> 4, j = i & 15;
            sA[r*17 + j] = x[(r0+r)*DIN + d0 + j];
        }
        for (int i = tid; i < 1024; i += 256) {
            int r = i >> 4, j = i & 15;
            sB[r*17 + j] = Wenc[(n0+r)*DIN + d0 + j];
        }
        __syncthreads();
#pragma unroll
        for (int j = 0; j < 16; j++) {
            float xa = sA[row*17 + j];
#pragma unroll
            for (int i = 0; i < 8; i++) acc[i] += xa * sB[(nb+i)*17 + j];
        }
        __syncthreads();
    }

    load_xtiles(sXC, sXS, n0);

#pragma unroll
    for (int i = 0; i < 8; i++) {
        float z  = acc[i] + benc[n0 + nb + i];
        float p0 = TWO_PI_F / (1.0f + expf(-z));
        int gi = (r0+row)*NN + n0 + nb + i;
        g_phi[gi]  = p0;
        g_phie[gi] = p0;
        float ss, cc;
        __sincosf(p0, &ss, &cc);
        sC[row*SC_STRIDE + nb + i] = cc;
        sS[row*SC_STRIDE + nb + i] = ss;
    }
    __syncthreads();
    m_tail(sC, sS, sXC, sXS, g_m[0], r0);
}

/* ================= fused per-eval kernel ================================ */
/* sub: RK4 substage; sAnc=A*sin(w tE), cAnc=A*cos(w tE) (host precomputed);
   cNext: coeff toward next eval point; buf rotation; doTail as before.     */
__global__ void __launch_bounds__(256, 1)
k_F(int sub, float sAnc, float cAnc, float cNext,
    int bufR, int bufW, int bufZ, int doTail) {
    extern __shared__ float sm[];
    float* sW  = sm;
    float* sXC = sm + SW_FLOATS;
    float* sXS = sXC + SX_FLOATS;
    float* sC  = sXS + SX_FLOATS;
    float* sS  = sC + SC_FLOATS;
    float* sR  = sS + SC_FLOATS;

    int n0 = blockIdx.x*64, r0 = blockIdx.y*32;
    int tid = threadIdx.x;

    /* zero this CTA's slice of the buffer used two evals ahead */
    {
        int cta = blockIdx.y*16 + blockIdx.x;
        g_m[bufZ][cta*256 + tid] = 0.f;
    }

    /* ---- P0: softmax over 128 patterns for our 32 rows ---- */
    {
        int row = tid >> 3, l8 = tid & 7;
        const float* mrow = &g_m[bufR][(r0+row)*PP];
        float a[16];
        float mx = -1e30f;
#pragma unroll
        for (int j = 0; j < 16; j++) {
            a[j] = mrow[l8 + (j << 3)] * BETA_N;
            mx = fmaxf(mx, a[j]);
        }
#pragma unroll
        for (int w = 1; w < 8; w <<= 1)
            mx = fmaxf(mx, __shfl_xor_sync(0xffffffffu, mx, w));
        float ssum = 0.f;
#pragma unroll
        for (int j = 0; j < 16; j++) { a[j] = __expf(a[j] - mx); ssum += a[j]; }
#pragma unroll
        for (int w = 1; w < 8; w <<= 1)
            ssum += __shfl_xor_sync(0xffffffffu, ssum, w);
        float inv = 1.0f / ssum;
#pragma unroll
        for (int j = 0; j < 16; j++)
            sW[row*SW_STRIDE + l8 + (j << 3)] = a[j] * inv;
    }

    load_xtiles(sXC, sXS, n0);
    __syncthreads();

    /* ---- P2: coupling GEMM, register tile 2 rows x 8 cols, K-split 2 ---- */
    int ks  = tid >> 7;            /* K-half: warps 0-3 = half 0, 4-7 = half 1 */
    int rb2 = (tid >> 3) & 15;     /* 16 row-pairs */
    int cb  = tid & 7;
    int nb  = cb*8;
    float wc[16], ws[16];
#pragma unroll
    for (int i = 0; i < 16; i++) { wc[i] = 0.f; ws[i] = 0.f; }
    {
        const float* w0 = &sW[(rb2*2)*SW_STRIDE + ks*64];
        const float* w1 = w0 + SW_STRIDE;
        const float* xc = &sXC[(ks*64)*SX_STRIDE + nb];
        const float* xs = &sXS[(ks*64)*SX_STRIDE + nb];
#pragma unroll 2
        for (int p = 0; p < 64; p++) {
            float wa = w0[p], wb = w1[p];
            float4 c0 = *(const float4*)&xc[0];
            float4 c1 = *(const float4*)&xc[4];
            float4 s0 = *(const float4*)&xs[0];
            float4 s1 = *(const float4*)&xs[4];
            xc += SX_STRIDE; xs += SX_STRIDE;
            wc[0]  += wa*c0.x; wc[1]  += wa*c0.y; wc[2]  += wa*c0.z; wc[3]  += wa*c0.w;
            wc[4]  += wa*c1.x; wc[5]  += wa*c1.y; wc[6]  += wa*c1.z; wc[7]  += wa*c1.w;
            wc[8]  += wb*c0.x; wc[9]  += wb*c0.y; wc[10] += wb*c0.z; wc[11] += wb*c0.w;
            wc[12] += wb*c1.x; wc[13] += wb*c1.y; wc[14] += wb*c1.z; wc[15] += wb*c1.w;
            ws[0]  += wa*s0.x; ws[1]  += wa*s0.y; ws[2]  += wa*s0.z; ws[3]  += wa*s0.w;
            ws[4]  += wa*s1.x; ws[5]  += wa*s1.y; ws[6]  += wa*s1.z; ws[7]  += wa*s1.w;
            ws[8]  += wb*s0.x; ws[9]  += wb*s0.y; ws[10] += wb*s0.z; ws[11] += wb*s0.w;
            ws[12] += wb*s1.x; ws[13] += wb*s1.y; ws[14] += wb*s1.z; ws[15] += wb*s1.w;
        }
    }
    if (ks == 1) {
        float* r = &sR[(tid - 128)*SR_STRIDE];
        *(float4*)&r[0]  = make_float4(wc[0],  wc[1],  wc[2],  wc[3]);
        *(float4*)&r[4]  = make_float4(wc[4],  wc[5],  wc[6],  wc[7]);
        *(float4*)&r[8]  = make_float4(wc[8],  wc[9],  wc[10], wc[11]);
        *(float4*)&r[12] = make_float4(wc[12], wc[13], wc[14], wc[15]);
        *(float4*)&r[16] = make_float4(ws[0],  ws[1],  ws[2],  ws[3]);
        *(float4*)&r[20] = make_float4(ws[4],  ws[5],  ws[6],  ws[7]);
        *(float4*)&r[24] = make_float4(ws[8],  ws[9],  ws[10], ws[11]);
        *(float4*)&r[28] = make_float4(ws[12], ws[13], ws[14], ws[15]);
    }
    __syncthreads();

    if (ks == 0) {
        const float* r = &sR[tid*SR_STRIDE];
#pragma unroll
        for (int i = 0; i < 16; i++) { wc[i] += r[i]; ws[i] += r[16 + i]; }

        /* ---- elementwise: anchor via angle identity; RK4 update ---- */
#pragma unroll
        for (int i = 0; i < 2; i++) {
            int row = rb2*2 + i;
            int g = (r0+row)*NN + n0 + nb;
            float4 pe0 = *(const float4*)&g_phie[g];
            float4 pe1 = *(const float4*)&g_phie[g+4];
            float pe[8] = {pe0.x, pe0.y, pe0.z, pe0.w, pe1.x, pe1.y, pe1.z, pe1.w};
            float kv[8];
#pragma unroll
            for (int j = 0; j < 8; j++) {
                float se, ce;
                __sincosf(pe[j], &se, &ce);
                /* A sin(wt - phi) = sAnc*ce - cAnc*se */
                kv[j] = fmaf(se, wc[i*8+j] - cAnc, fmaf(ce, sAnc - ws[i*8+j], 0.f));
            }
            float phiN[8];
            if (sub == 0) {
                *(float4*)&g_acc[g]   = make_float4(kv[0], kv[1], kv[2], kv[3]);
                *(float4*)&g_acc[g+4] = make_float4(kv[4], kv[5], kv[6], kv[7]);
                float4 p0 = *(const float4*)&g_phi[g];
                float4 p1 = *(const float4*)&g_phi[g+4];
                float ph[8] = {p0.x, p0.y, p0.z, p0.w, p1.x, p1.y, p1.z, p1.w};
#pragma unroll
                for (int j = 0; j < 8; j++) phiN[j] = fmaf(cNext, kv[j], ph[j]);
            } else if (sub == 3) {
                float4 a0 = *(const float4*)&g_acc[g];
                float4 a1 = *(const float4*)&g_acc[g+4];
                float av[8] = {a0.x, a0.y, a0.z, a0.w, a1.x, a1.y, a1.z, a1.w};
                float4 p0 = *(const float4*)&g_phi[g];
                float4 p1 = *(const float4*)&g_phi[g+4];
                float ph[8] = {p0.x, p0.y, p0.z, p0.w, p1.x, p1.y, p1.z, p1.w};
#pragma unroll
                for (int j = 0; j < 8; j++)
                    phiN[j] = fmaf(DT/6.0f, av[j] + kv[j], ph[j]);
                *(float4*)&g_phi[g]   = make_float4(phiN[0], phiN[1], phiN[2], phiN[3]);
                *(float4*)&g_phi[g+4] = make_float4(phiN[4], phiN[5], phiN[6], phiN[7]);
            } else {
                float4 a0 = *(const float4*)&g_acc[g];
                float4 a1 = *(const float4*)&g_acc[g+4];
                float av[8] = {a0.x, a0.y, a0.z, a0.w, a1.x, a1.y, a1.z, a1.w};
#pragma unroll
                for (int j = 0; j < 8; j++) av[j] = fmaf(2.0f, kv[j], av[j]);
                *(float4*)&g_acc[g]   = make_float4(av[0], av[1], av[2], av[3]);
                *(float4*)&g_acc[g+4] = make_float4(av[4], av[5], av[6], av[7]);
                float4 p0 = *(const float4*)&g_phi[g];
                float4 p1 = *(const float4*)&g_phi[g+4];
                float ph[8] = {p0.x, p0.y, p0.z, p0.w, p1.x, p1.y, p1.z, p1.w};
#pragma unroll
                for (int j = 0; j < 8; j++) phiN[j] = fmaf(cNext, kv[j], ph[j]);
            }
            *(float4*)&g_phie[g]   = make_float4(phiN[0], phiN[1], phiN[2], phiN[3]);
            *(float4*)&g_phie[g+4] = make_float4(phiN[4], phiN[5], phiN[6], phiN[7]);

            if (doTail) {
#pragma unroll
                for (int j = 0; j < 8; j++) {
                    float sn, cn;
                    __sincosf(phiN[j], &sn, &cn);
                    sC[row*SC_STRIDE + nb + j] = cn;
                    sS[row*SC_STRIDE + nb + j] = sn;
                }
            }
        }
    }

    /* ---- tail: next-eval features -> partial m (all 256 threads) ---- */
    if (doTail) {
        __syncthreads();
        m_tail(sC, sS, sXC, sXS, g_m[bufW], r0);
    }
}

/* ================= readout: [cos(phi), sin(phi)] @ Wout^T + b =========== */
__global__ void k_readout(const float* __restrict__ Wout,
                          const float* __restrict__ bout,
                          float* __restrict__ out) {
    __shared__ float red[256];
    int b = blockIdx.x, tid = threadIdx.x;
    float acc[COUT];
#pragma unroll
    for (int c = 0; c < COUT; c++) acc[c] = 0.f;

#pragma unroll
    for (int it = 0; it < 4; it++) {
        int n = tid + it*256;
        float phi = g_phi[b*NN + n];
        float s, c;
        sincosf(phi, &s, &c);     /* accurate: feeds output directly */
#pragma unroll
        for (int cls = 0; cls < COUT; cls++)
            acc[cls] += c*Wout[cls*(2*NN) + n] + s*Wout[cls*(2*NN) + NN + n];
    }
    for (int cls = 0; cls < COUT; cls++) {
        red[tid] = acc[cls];
        __syncthreads();
        for (int off = 128; off > 0; off >>= 1) {
            if (tid < off) red[tid] += red[tid + off];
            __syncthreads();
        }
        if (tid == 0) out[b*COUT + cls] = red[0] + bout[cls];
        __syncthreads();
    }
}

/* ================= host ================================================= */
extern "C" void kernel_launch(void* const* d_in, const int* in_sizes, int n_in,
                              void* d_out, int out_size) {
    (void)in_sizes; (void)n_in; (void)out_size;
    const float* x    = (const float*)d_in[0];
    const float* Wenc = (const float*)d_in[1];
    const float* benc = (const float*)d_in[2];
    const float* xi   = (const float*)d_in[3];
    const float* Wout = (const float*)d_in[4];
    const float* bout = (const float*)d_in[5];
    float* out = (float*)d_out;

    cudaFuncSetAttribute(k_encoder, cudaFuncAttributeMaxDynamicSharedMemorySize, SMEM_BYTES);
    cudaFuncSetAttribute(k_F,       cudaFuncAttributeMaxDynamicSharedMemorySize, SMEM_BYTES);

    k_init<<<512, 256>>>(xi);

    dim3 grid(16, 8);
    k_encoder<<<grid, 256, SMEM_BYTES>>>(x, Wenc, benc);

    for (int e = 0; e < 64; e++) {
        int step = e >> 2, sub = e & 3;
        float t0 = (float)step * DT;
        float tE = (sub == 0) ? t0 : ((sub == 3) ? t0 + DT : t0 + 0.5f*DT);
        float cNext = (sub == 2) ? DT : 0.5f*DT;
        /* anchor phase, fp32 arg rounding to match reference, accurate sin */
        float argf = OME * tE;
        double sa = sin((double)argf), ca = cos((double)argf);
        float sAnc = (float)((double)A_ANC * sa);
        float cAnc = (float)((double)A_ANC * ca);
        int bufR = e % 3, bufW = (e + 1) % 3, bufZ = (e + 2) % 3;
        int doTail = (e < 63) ? 1 : 0;
        k_F<<<grid, 256, SMEM_BYTES>>>(sub, sAnc, cAnc, cNext,
                                       bufR, bufW, bufZ, doTail);
    }

    k_readout<<<BATCH, 256>>>(Wout, bout, out);
}

// round 5
// speedup vs baseline: 2.3718x; 1.3460x over previous
#include <cuda_runtime.h>
#include <math.h>

#define BATCH 256
#define NN    1024
#define PP    128
#define DIN   784
#define COUT  10
#define CH    32                     /* columns per CTA */

#define TWO_PI_F 6.283185307179586f
#define DT       0.03125f            /* T/N_STEPS = 0.5/16, exact in fp32 */
#define BETA_N   (2.0f/1024.0f)
#define A_ANC    0.08f
#define OME      (TWO_PI_F*200.0f)

/* ---- device scratch (static globals; no allocation allowed) ---- */
__device__ float g_xc[PP*NN];     /* cos(xi) [p][n] */
__device__ float g_xs[PP*NN];     /* sin(xi) [p][n] */
__device__ float g_phi[BATCH*NN];   /* base state */
__device__ float g_phie[BATCH*NN];  /* eval point */
__device__ float g_acc[BATCH*NN];   /* RK4 accumulator */
__device__ float g_m[3][BATCH*PP];  /* rotating overlap buffers */

/* ---- shared layout (floats) ---- */
#define SW_STRIDE 130                /* w tile [32][130] */
#define SX_STRIDE 36                 /* xc/xs tiles [128][36] */
#define SC_STRIDE 36                 /* c/s tiles [32][36] */
#define SR_STRIDE 36                 /* reduction: 192 writers x 36 */
#define SW_FLOATS (32*SW_STRIDE)     /* 4160 */
#define SX_FLOATS (128*SX_STRIDE)    /* 4608 */
#define SC_FLOATS (32*SC_STRIDE)     /* 1152 */
#define SR_FLOATS (192*SR_STRIDE)    /* 6912 */
#define SMEM_FLOATS (SW_FLOATS + 2*SX_FLOATS + 2*SC_FLOATS + SR_FLOATS)
#define SMEM_BYTES  (SMEM_FLOATS*4)  /* 90368 bytes -> 2 CTAs/SM */

/* ================= init: cos/sin of xi + zero first two m buffers ======= */
__global__ void k_init(const float* __restrict__ xi) {
    int i = blockIdx.x*256 + threadIdx.x;
    if (i < PP*NN) {
        float v = xi[i];
        g_xc[i] = cosf(v);
        g_xs[i] = sinf(v);
    }
    if (i < BATCH*PP) { g_m[0][i] = 0.f; g_m[1][i] = 0.f; }
}

/* load xc/xs tiles [128 p][32 n] for column chunk n0 into shared */
__device__ __forceinline__ void load_xtiles(float* sXC, float* sXS, int n0) {
    for (int i = threadIdx.x; i < 128*8; i += 256) {
        int p = i >> 3, q = (i & 7) << 2;
        float4 a = *(const float4*)&g_xc[p*NN + n0 + q];
        *(float4*)&sXC[p*SX_STRIDE + q] = a;
        float4 b = *(const float4*)&g_xs[p*NN + n0 + q];
        *(float4*)&sXS[p*SX_STRIDE + q] = b;
    }
}

/* partial m over this CTA's 32-col chunk, atomicAdd into mbuf.
   4 rows x 4 patterns per thread; float4 over n. rb=tid>>5, pb=tid&31. */
__device__ __forceinline__ void m_tail(const float* sC, const float* sS,
                                       const float* sXC, const float* sXS,
                                       float* mbuf, int r0) {
    int rb = threadIdx.x >> 5;
    int pb = threadIdx.x & 31;
    float acc[16];
#pragma unroll
    for (int i = 0; i < 16; i++) acc[i] = 0.f;
    const float* cB = sC + (rb*4)*SC_STRIDE;
    const float* sB = sS + (rb*4)*SC_STRIDE;
#pragma unroll
    for (int n = 0; n < CH; n += 4) {
        float4 cr[4], sr[4];
#pragma unroll
        for (int r = 0; r < 4; r++) {
            cr[r] = *(const float4*)&cB[r*SC_STRIDE + n];
            sr[r] = *(const float4*)&sB[r*SC_STRIDE + n];
        }
#pragma unroll
        for (int j = 0; j < 4; j++) {
            int p = pb + (j << 5);
            float4 xc4 = *(const float4*)&sXC[p*SX_STRIDE + n];
            float4 xs4 = *(const float4*)&sXS[p*SX_STRIDE + n];
#pragma unroll
            for (int r = 0; r < 4; r++) {
                float t = acc[j*4 + r];
                t = fmaf(cr[r].x, xc4.x, t); t = fmaf(sr[r].x, xs4.x, t);
                t = fmaf(cr[r].y, xc4.y, t); t = fmaf(sr[r].y, xs4.y, t);
                t = fmaf(cr[r].z, xc4.z, t); t = fmaf(sr[r].z, xs4.z, t);
                t = fmaf(cr[r].w, xc4.w, t); t = fmaf(sr[r].w, xs4.w, t);
                acc[j*4 + r] = t;
            }
        }
    }
#pragma unroll
    for (int j = 0; j < 4; j++)
#pragma unroll
        for (int r = 0; r < 4; r++)
            atomicAdd(&mbuf[(r0 + rb*4 + r)*PP + pb + (j << 5)], acc[j*4 + r]);
}

/* ================= encoder: phi0 = 2pi*sigmoid(x @ Wenc^T + b), + m0 ==== */
__global__ void __launch_bounds__(256, 2)
k_encoder(const float* __restrict__ x,
          const float* __restrict__ Wenc,
          const float* __restrict__ benc) {
    extern __shared__ float sm[];
    float* sA  = sm;                 /* [32][17] staging, aliases sW region */
    float* sB  = sm + 32*17;         /* [32][17] */
    float* sXC = sm + SW_FLOATS;
    float* sXS = sXC + SX_FLOATS;
    float* sC  = sXS + SX_FLOATS;
    float* sS  = sC + SC_FLOATS;

    int n0 = blockIdx.x*CH, r0 = blockIdx.y*32;
    int tid = threadIdx.x;
    int row = tid >> 3, ng = tid & 7, nb = ng*4;

    float acc[4];
#pragma unroll
    for (int i = 0; i < 4; i++) acc[i] = 0.f;

    for (int d0 = 0; d0 < DIN; d0 += 16) {
        for (int i = tid; i < 512; i += 256) {
            int r = i >> 4, j = i & 15;
            sA[r*17 + j] = x[(r0+r)*DIN + d0 + j];
            sB[r*17 + j] = Wenc[(n0+r)*DIN + d0 + j];
        }
        __syncthreads();
#pragma unroll
        for (int j = 0; j < 16; j++) {
            float xa = sA[row*17 + j];
#pragma unroll
            for (int i = 0; i < 4; i++) acc[i] += xa * sB[(nb+i)*17 + j];
        }
        __syncthreads();
    }

    load_xtiles(sXC, sXS, n0);

#pragma unroll
    for (int i = 0; i < 4; i++) {
        float z  = acc[i] + benc[n0 + nb + i];
        float p0 = TWO_PI_F / (1.0f + expf(-z));
        int gi = (r0+row)*NN + n0 + nb + i;
        g_phi[gi]  = p0;
        g_phie[gi] = p0;
        float ss, cc;
        __sincosf(p0, &ss, &cc);
        sC[row*SC_STRIDE + nb + i] = cc;
        sS[row*SC_STRIDE + nb + i] = ss;
    }
    __syncthreads();
    m_tail(sC, sS, sXC, sXS, g_m[0], r0);
}

/* ================= fused per-eval kernel ================================ */
__global__ void __launch_bounds__(256, 2)
k_F(int sub, float sAnc, float cAnc, float cNext,
    int bufR, int bufW, int bufZ, int doTail) {
    extern __shared__ float sm[];
    float* sW  = sm;
    float* sXC = sm + SW_FLOATS;
    float* sXS = sXC + SX_FLOATS;
    float* sC  = sXS + SX_FLOATS;
    float* sS  = sC + SC_FLOATS;
    float* sR  = sS + SC_FLOATS;

    int n0 = blockIdx.x*CH, r0 = blockIdx.y*32;
    int tid = threadIdx.x;

    /* zero this CTA's slice of the buffer used two evals ahead */
    {
        int cta = blockIdx.y*32 + blockIdx.x;          /* 0..255 */
        if (tid < 128) g_m[bufZ][cta*128 + tid] = 0.f;
    }

    /* ---- P0: softmax over 128 patterns for our 32 rows ---- */
    {
        int row = tid >> 3, l8 = tid & 7;
        const float* mrow = &g_m[bufR][(r0+row)*PP];
        float a[16];
        float mx = -1e30f;
#pragma unroll
        for (int j = 0; j < 16; j++) {
            a[j] = mrow[l8 + (j << 3)] * BETA_N;
            mx = fmaxf(mx, a[j]);
        }
#pragma unroll
        for (int w = 1; w < 8; w <<= 1)
            mx = fmaxf(mx, __shfl_xor_sync(0xffffffffu, mx, w));
        float ssum = 0.f;
#pragma unroll
        for (int j = 0; j < 16; j++) { a[j] = __expf(a[j] - mx); ssum += a[j]; }
#pragma unroll
        for (int w = 1; w < 8; w <<= 1)
            ssum += __shfl_xor_sync(0xffffffffu, ssum, w);
        float inv = 1.0f / ssum;
#pragma unroll
        for (int j = 0; j < 16; j++)
            sW[row*SW_STRIDE + l8 + (j << 3)] = a[j] * inv;
    }

    load_xtiles(sXC, sXS, n0);
    __syncthreads();

    /* ---- P2: coupling GEMM, tile 2 rows x 8 cols, K-split 4 ----
       ks = tid>>6 (K quarter), rb2 = (tid>>2)&15 (rowpair), cb = tid&3 */
    int ks  = tid >> 6;
    int rb2 = (tid >> 2) & 15;
    int cb  = tid & 3;
    int nb  = cb*8;
    float wc[16], ws[16];
#pragma unroll
    for (int i = 0; i < 16; i++) { wc[i] = 0.f; ws[i] = 0.f; }
    {
        const float* w0 = &sW[(rb2*2)*SW_STRIDE + ks*32];
        const float* w1 = w0 + SW_STRIDE;
        const float* xc = &sXC[(ks*32)*SX_STRIDE + nb];
        const float* xs = &sXS[(ks*32)*SX_STRIDE + nb];
#pragma unroll 2
        for (int p = 0; p < 32; p++) {
            float wa = w0[p], wb = w1[p];
            float4 c0 = *(const float4*)&xc[0];
            float4 c1 = *(const float4*)&xc[4];
            float4 s0 = *(const float4*)&xs[0];
            float4 s1 = *(const float4*)&xs[4];
            xc += SX_STRIDE; xs += SX_STRIDE;
            wc[0]  += wa*c0.x; wc[1]  += wa*c0.y; wc[2]  += wa*c0.z; wc[3]  += wa*c0.w;
            wc[4]  += wa*c1.x; wc[5]  += wa*c1.y; wc[6]  += wa*c1.z; wc[7]  += wa*c1.w;
            wc[8]  += wb*c0.x; wc[9]  += wb*c0.y; wc[10] += wb*c0.z; wc[11] += wb*c0.w;
            wc[12] += wb*c1.x; wc[13] += wb*c1.y; wc[14] += wb*c1.z; wc[15] += wb*c1.w;
            ws[0]  += wa*s0.x; ws[1]  += wa*s0.y; ws[2]  += wa*s0.z; ws[3]  += wa*s0.w;
            ws[4]  += wa*s1.x; ws[5]  += wa*s1.y; ws[6]  += wa*s1.z; ws[7]  += wa*s1.w;
            ws[8]  += wb*s0.x; ws[9]  += wb*s0.y; ws[10] += wb*s0.z; ws[11] += wb*s0.w;
            ws[12] += wb*s1.x; ws[13] += wb*s1.y; ws[14] += wb*s1.z; ws[15] += wb*s1.w;
        }
    }
    if (ks != 0) {
        float* r = &sR[((ks-1)*64 + (tid & 63))*SR_STRIDE];
        *(float4*)&r[0]  = make_float4(wc[0],  wc[1],  wc[2],  wc[3]);
        *(float4*)&r[4]  = make_float4(wc[4],  wc[5],  wc[6],  wc[7]);
        *(float4*)&r[8]  = make_float4(wc[8],  wc[9],  wc[10], wc[11]);
        *(float4*)&r[12] = make_float4(wc[12], wc[13], wc[14], wc[15]);
        *(float4*)&r[16] = make_float4(ws[0],  ws[1],  ws[2],  ws[3]);
        *(float4*)&r[20] = make_float4(ws[4],  ws[5],  ws[6],  ws[7]);
        *(float4*)&r[24] = make_float4(ws[8],  ws[9],  ws[10], ws[11]);
        *(float4*)&r[28] = make_float4(ws[12], ws[13], ws[14], ws[15]);
    }
    __syncthreads();

    if (ks == 0) {
#pragma unroll
        for (int part = 0; part < 3; part++) {
            const float* r = &sR[(part*64 + tid)*SR_STRIDE];
#pragma unroll
            for (int i = 0; i < 16; i++) { wc[i] += r[i]; ws[i] += r[16 + i]; }
        }

        /* ---- elementwise: anchor via angle identity; RK4 update ---- */
#pragma unroll
        for (int i = 0; i < 2; i++) {
            int row = rb2*2 + i;
            int g = (r0+row)*NN + n0 + nb;
            float4 pe0 = *(const float4*)&g_phie[g];
            float4 pe1 = *(const float4*)&g_phie[g+4];
            float pe[8] = {pe0.x, pe0.y, pe0.z, pe0.w, pe1.x, pe1.y, pe1.z, pe1.w};
            float kv[8];
#pragma unroll
            for (int j = 0; j < 8; j++) {
                float se, ce;
                __sincosf(pe[j], &se, &ce);
                /* A sin(wt - phi) = sAnc*ce - cAnc*se */
                kv[j] = fmaf(se, wc[i*8+j] - cAnc, ce * (sAnc - ws[i*8+j]));
            }
            float phiN[8];
            if (sub == 0) {
                *(float4*)&g_acc[g]   = make_float4(kv[0], kv[1], kv[2], kv[3]);
                *(float4*)&g_acc[g+4] = make_float4(kv[4], kv[5], kv[6], kv[7]);
                float4 p0 = *(const float4*)&g_phi[g];
                float4 p1 = *(const float4*)&g_phi[g+4];
                float ph[8] = {p0.x, p0.y, p0.z, p0.w, p1.x, p1.y, p1.z, p1.w};
#pragma unroll
                for (int j = 0; j < 8; j++) phiN[j] = fmaf(cNext, kv[j], ph[j]);
            } else if (sub == 3) {
                float4 a0 = *(const float4*)&g_acc[g];
                float4 a1 = *(const float4*)&g_acc[g+4];
                float av[8] = {a0.x, a0.y, a0.z, a0.w, a1.x, a1.y, a1.z, a1.w};
                float4 p0 = *(const float4*)&g_phi[g];
                float4 p1 = *(const float4*)&g_phi[g+4];
                float ph[8] = {p0.x, p0.y, p0.z, p0.w, p1.x, p1.y, p1.z, p1.w};
#pragma unroll
                for (int j = 0; j < 8; j++)
                    phiN[j] = fmaf(DT/6.0f, av[j] + kv[j], ph[j]);
                *(float4*)&g_phi[g]   = make_float4(phiN[0], phiN[1], phiN[2], phiN[3]);
                *(float4*)&g_phi[g+4] = make_float4(phiN[4], phiN[5], phiN[6], phiN[7]);
            } else {
                float4 a0 = *(const float4*)&g_acc[g];
                float4 a1 = *(const float4*)&g_acc[g+4];
                float av[8] = {a0.x, a0.y, a0.z, a0.w, a1.x, a1.y, a1.z, a1.w};
#pragma unroll
                for (int j = 0; j < 8; j++) av[j] = fmaf(2.0f, kv[j], av[j]);
                *(float4*)&g_acc[g]   = make_float4(av[0], av[1], av[2], av[3]);
                *(float4*)&g_acc[g+4] = make_float4(av[4], av[5], av[6], av[7]);
                float4 p0 = *(const float4*)&g_phi[g];
                float4 p1 = *(const float4*)&g_phi[g+4];
                float ph[8] = {p0.x, p0.y, p0.z, p0.w, p1.x, p1.y, p1.z, p1.w};
#pragma unroll
                for (int j = 0; j < 8; j++) phiN[j] = fmaf(cNext, kv[j], ph[j]);
            }
            *(float4*)&g_phie[g]   = make_float4(phiN[0], phiN[1], phiN[2], phiN[3]);
            *(float4*)&g_phie[g+4] = make_float4(phiN[4], phiN[5], phiN[6], phiN[7]);

            if (doTail) {
#pragma unroll
                for (int j = 0; j < 8; j++) {
                    float sn, cn;
                    __sincosf(phiN[j], &sn, &cn);
                    sC[row*SC_STRIDE + nb + j] = cn;
                    sS[row*SC_STRIDE + nb + j] = sn;
                }
            }
        }
    }

    /* ---- tail: next-eval features -> partial m (all 256 threads) ---- */
    if (doTail) {
        __syncthreads();
        m_tail(sC, sS, sXC, sXS, g_m[bufW], r0);
    }
}

/* ================= readout: [cos(phi), sin(phi)] @ Wout^T + b =========== */
__global__ void k_readout(const float* __restrict__ Wout,
                          const float* __restrict__ bout,
                          float* __restrict__ out) {
    __shared__ float red[256];
    int b = blockIdx.x, tid = threadIdx.x;
    float acc[COUT];
#pragma unroll
    for (int c = 0; c < COUT; c++) acc[c] = 0.f;

#pragma unroll
    for (int it = 0; it < 4; it++) {
        int n = tid + it*256;
        float phi = g_phi[b*NN + n];
        float s, c;
        sincosf(phi, &s, &c);     /* accurate: feeds output directly */
#pragma unroll
        for (int cls = 0; cls < COUT; cls++)
            acc[cls] += c*Wout[cls*(2*NN) + n] + s*Wout[cls*(2*NN) + NN + n];
    }
    for (int cls = 0; cls < COUT; cls++) {
        red[tid] = acc[cls];
        __syncthreads();
        for (int off = 128; off > 0; off >>= 1) {
            if (tid < off) red[tid] += red[tid + off];
            __syncthreads();
        }
        if (tid == 0) out[b*COUT + cls] = red[0] + bout[cls];
        __syncthreads();
    }
}

/* ================= host ================================================= */
extern "C" void kernel_launch(void* const* d_in, const int* in_sizes, int n_in,
                              void* d_out, int out_size) {
    (void)in_sizes; (void)n_in; (void)out_size;
    const float* x    = (const float*)d_in[0];
    const float* Wenc = (const float*)d_in[1];
    const float* benc = (const float*)d_in[2];
    const float* xi   = (const float*)d_in[3];
    const float* Wout = (const float*)d_in[4];
    const float* bout = (const float*)d_in[5];
    float* out = (float*)d_out;

    cudaFuncSetAttribute(k_encoder, cudaFuncAttributeMaxDynamicSharedMemorySize, SMEM_BYTES);
    cudaFuncSetAttribute(k_F,       cudaFuncAttributeMaxDynamicSharedMemorySize, SMEM_BYTES);

    k_init<<<512, 256>>>(xi);

    dim3 grid(NN/CH, 8);             /* 32 x 8 = 256 CTAs */
    k_encoder<<<grid, 256, SMEM_BYTES>>>(x, Wenc, benc);

    for (int e = 0; e < 64; e++) {
        int step = e >> 2, sub = e & 3;
        float t0 = (float)step * DT;
        float tE = (sub == 0) ? t0 : ((sub == 3) ? t0 + DT : t0 + 0.5f*DT);
        float cNext = (sub == 2) ? DT : 0.5f*DT;
        /* anchor phase: fp32 arg rounding to match reference, accurate sin */
        float argf = OME * tE;
        double sa = sin((double)argf), ca = cos((double)argf);
        float sAnc = (float)((double)A_ANC * sa);
        float cAnc = (float)((double)A_ANC * ca);
        int bufR = e % 3, bufW = (e + 1) % 3, bufZ = (e + 2) % 3;
        int doTail = (e < 63) ? 1 : 0;
        k_F<<<grid, 256, SMEM_BYTES>>>(sub, sAnc, cAnc, cNext,
                                       bufR, bufW, bufZ, doTail);
    }

    k_readout<<<BATCH, 256>>>(Wout, bout, out);
}

// round 6
// speedup vs baseline: 2.4951x; 1.0520x over previous
#include <cuda_runtime.h>
#include <math.h>

#define BATCH 256
#define NN    1024
#define PP    128
#define DIN   784
#define COUT  10
#define CH    32                     /* columns per CTA */

#define TWO_PI_F 6.283185307179586f
#define DT       0.03125f            /* T/N_STEPS = 0.5/16, exact in fp32 */
#define BETA_N   (2.0f/1024.0f)
#define A_ANC    0.08f
#define OME      (TWO_PI_F*200.0f)

/* ---- device scratch (static globals; no allocation allowed) ---- */
__device__ float g_xc[PP*NN];       /* cos(xi) [p][n] */
__device__ float g_xs[PP*NN];       /* sin(xi) [p][n] */
__device__ float g_phi[BATCH*NN];   /* base state */
__device__ float g_fc[BATCH*NN];    /* cos(phi_eval) features */
__device__ float g_fs[BATCH*NN];    /* sin(phi_eval) features */
__device__ float g_acc[BATCH*NN];   /* RK4 accumulator */
__device__ float g_m[3][BATCH*PP];  /* rotating overlap buffers */

/* ---- shared layout (floats) ---- */
#define SW_STRIDE 130                /* w tile [32][130] */
#define SX_STRIDE 36                 /* xc/xs tiles [128][36] */
#define SC_STRIDE 36                 /* c/s tiles [32][36] */
#define SR_STRIDE 36                 /* reduction: 256 writers x 36 */
#define SW_FLOATS (32*SW_STRIDE)     /* 4160 */
#define SX_FLOATS (128*SX_STRIDE)    /* 4608 */
#define SC_FLOATS (32*SC_STRIDE)     /* 1152 */
#define SR_FLOATS (256*SR_STRIDE)    /* 9216 */
#define SMEM_FLOATS (SW_FLOATS + 2*SX_FLOATS + 2*SC_FLOATS + SR_FLOATS)
#define SMEM_BYTES  (SMEM_FLOATS*4)  /* 99584 bytes -> 2 CTAs/SM */

/* ================= init: cos/sin of xi + zero first two m buffers ======= */
__global__ void k_init(const float* __restrict__ xi) {
    int i = blockIdx.x*256 + threadIdx.x;
    if (i < PP*NN) {
        float v = xi[i];
        g_xc[i] = cosf(v);
        g_xs[i] = sinf(v);
    }
    if (i < BATCH*PP) { g_m[0][i] = 0.f; g_m[1][i] = 0.f; }
}

/* load xc/xs tiles [128 p][32 n] for column chunk n0 into shared */
__device__ __forceinline__ void load_xtiles(float* sXC, float* sXS, int n0) {
    for (int i = threadIdx.x; i < 128*8; i += 256) {
        int p = i >> 3, q = (i & 7) << 2;
        float4 a = *(const float4*)&g_xc[p*NN + n0 + q];
        *(float4*)&sXC[p*SX_STRIDE + q] = a;
        float4 b = *(const float4*)&g_xs[p*NN + n0 + q];
        *(float4*)&sXS[p*SX_STRIDE + q] = b;
    }
}

/* partial m over this CTA's 32-col chunk, atomicAdd into mbuf.
   4 rows x 4 patterns per thread; float4 over n. rb=tid>>5, pb=tid&31. */
__device__ __forceinline__ void m_tail(const float* sC, const float* sS,
                                       const float* sXC, const float* sXS,
                                       float* mbuf, int r0) {
    int rb = threadIdx.x >> 5;
    int pb = threadIdx.x & 31;
    float acc[16];
#pragma unroll
    for (int i = 0; i < 16; i++) acc[i] = 0.f;
    const float* cB = sC + (rb*4)*SC_STRIDE;
    const float* sB = sS + (rb*4)*SC_STRIDE;
#pragma unroll
    for (int n = 0; n < CH; n += 4) {
        float4 cr[4], sr[4];
#pragma unroll
        for (int r = 0; r < 4; r++) {
            cr[r] = *(const float4*)&cB[r*SC_STRIDE + n];
            sr[r] = *(const float4*)&sB[r*SC_STRIDE + n];
        }
#pragma unroll
        for (int j = 0; j < 4; j++) {
            int p = pb + (j << 5);
            float4 xc4 = *(const float4*)&sXC[p*SX_STRIDE + n];
            float4 xs4 = *(const float4*)&sXS[p*SX_STRIDE + n];
#pragma unroll
            for (int r = 0; r < 4; r++) {
                float t = acc[j*4 + r];
                t = fmaf(cr[r].x, xc4.x, t); t = fmaf(sr[r].x, xs4.x, t);
                t = fmaf(cr[r].y, xc4.y, t); t = fmaf(sr[r].y, xs4.y, t);
                t = fmaf(cr[r].z, xc4.z, t); t = fmaf(sr[r].z, xs4.z, t);
                t = fmaf(cr[r].w, xc4.w, t); t = fmaf(sr[r].w, xs4.w, t);
                acc[j*4 + r] = t;
            }
        }
    }
#pragma unroll
    for (int j = 0; j < 4; j++)
#pragma unroll
        for (int r = 0; r < 4; r++)
            atomicAdd(&mbuf[(r0 + rb*4 + r)*PP + pb + (j << 5)], acc[j*4 + r]);
}

/* ================= encoder: phi0 = 2pi*sigmoid(x @ Wenc^T + b), + m0 ==== */
__global__ void __launch_bounds__(256, 2)
k_encoder(const float* __restrict__ x,
          const float* __restrict__ Wenc,
          const float* __restrict__ benc) {
    extern __shared__ float sm[];
    float* sA  = sm;                 /* [32][17] staging, aliases sW region */
    float* sB  = sm + 32*17;         /* [32][17] */
    float* sXC = sm + SW_FLOATS;
    float* sXS = sXC + SX_FLOATS;
    float* sC  = sXS + SX_FLOATS;
    float* sS  = sC + SC_FLOATS;

    int n0 = blockIdx.x*CH, r0 = blockIdx.y*32;
    int tid = threadIdx.x;
    int row = tid >> 3, ng = tid & 7, nb = ng*4;

    float acc[4];
#pragma unroll
    for (int i = 0; i < 4; i++) acc[i] = 0.f;

    for (int d0 = 0; d0 < DIN; d0 += 16) {
        for (int i = tid; i < 512; i += 256) {
            int r = i >> 4, j = i & 15;
            sA[r*17 + j] = x[(r0+r)*DIN + d0 + j];
            sB[r*17 + j] = Wenc[(n0+r)*DIN + d0 + j];
        }
        __syncthreads();
#pragma unroll
        for (int j = 0; j < 16; j++) {
            float xa = sA[row*17 + j];
#pragma unroll
            for (int i = 0; i < 4; i++) acc[i] += xa * sB[(nb+i)*17 + j];
        }
        __syncthreads();
    }

    load_xtiles(sXC, sXS, n0);

#pragma unroll
    for (int i = 0; i < 4; i++) {
        float z  = acc[i] + benc[n0 + nb + i];
        float p0 = TWO_PI_F / (1.0f + expf(-z));
        int gi = (r0+row)*NN + n0 + nb + i;
        g_phi[gi]  = p0;
        float ss, cc;
        __sincosf(p0, &ss, &cc);
        g_fc[gi] = cc;
        g_fs[gi] = ss;
        sC[row*SC_STRIDE + nb + i] = cc;
        sS[row*SC_STRIDE + nb + i] = ss;
    }
    __syncthreads();
    m_tail(sC, sS, sXC, sXS, g_m[0], r0);
}

/* ================= fused per-eval kernel ================================ */
__global__ void __launch_bounds__(256, 2)
k_F(int sub, float sAnc, float cAnc, float cNext,
    int bufR, int bufW, int bufZ, int doTail) {
    extern __shared__ float sm[];
    float* sW  = sm;
    float* sXC = sm + SW_FLOATS;
    float* sXS = sXC + SX_FLOATS;
    float* sC  = sXS + SX_FLOATS;
    float* sS  = sC + SC_FLOATS;
    float* sR  = sS + SC_FLOATS;

    int n0 = blockIdx.x*CH, r0 = blockIdx.y*32;
    int tid = threadIdx.x;

    /* zero this CTA's slice of the buffer used two evals ahead */
    {
        int cta = blockIdx.y*32 + blockIdx.x;          /* 0..255 */
        if (tid < 128) g_m[bufZ][cta*128 + tid] = 0.f;
    }

    /* ---- P0: softmax over 128 patterns (arg in [-2,2]: no max shift) ---- */
    {
        int row = tid >> 3, l8 = tid & 7;
        const float* mrow = &g_m[bufR][(r0+row)*PP];
        float a[16];
        float ssum = 0.f;
#pragma unroll
        for (int j = 0; j < 16; j++) {
            a[j] = __expf(mrow[l8 + (j << 3)] * BETA_N);
            ssum += a[j];
        }
#pragma unroll
        for (int w = 1; w < 8; w <<= 1)
            ssum += __shfl_xor_sync(0xffffffffu, ssum, w);
        float inv = 1.0f / ssum;
#pragma unroll
        for (int j = 0; j < 16; j++)
            sW[row*SW_STRIDE + l8 + (j << 3)] = a[j] * inv;
    }

    load_xtiles(sXC, sXS, n0);
    __syncthreads();

    /* ---- P2: coupling GEMM, tile 2 rows x 8 cols, K-split 4 ----
       ks = tid>>6 (K quarter), rb2 = (tid>>2)&15 (rowpair), cb = tid&3 */
    {
        int ks  = tid >> 6;
        int rb2 = (tid >> 2) & 15;
        int cb  = tid & 3;
        int nb  = cb*8;
        float wc[16], ws[16];
#pragma unroll
        for (int i = 0; i < 16; i++) { wc[i] = 0.f; ws[i] = 0.f; }
        const float* w0 = &sW[(rb2*2)*SW_STRIDE + ks*32];
        const float* w1 = w0 + SW_STRIDE;
        const float* xc = &sXC[(ks*32)*SX_STRIDE + nb];
        const float* xs = &sXS[(ks*32)*SX_STRIDE + nb];
#pragma unroll 2
        for (int p = 0; p < 32; p++) {
            float wa = w0[p], wb = w1[p];
            float4 c0 = *(const float4*)&xc[0];
            float4 c1 = *(const float4*)&xc[4];
            float4 s0 = *(const float4*)&xs[0];
            float4 s1 = *(const float4*)&xs[4];
            xc += SX_STRIDE; xs += SX_STRIDE;
            wc[0]  += wa*c0.x; wc[1]  += wa*c0.y; wc[2]  += wa*c0.z; wc[3]  += wa*c0.w;
            wc[4]  += wa*c1.x; wc[5]  += wa*c1.y; wc[6]  += wa*c1.z; wc[7]  += wa*c1.w;
            wc[8]  += wb*c0.x; wc[9]  += wb*c0.y; wc[10] += wb*c0.z; wc[11] += wb*c0.w;
            wc[12] += wb*c1.x; wc[13] += wb*c1.y; wc[14] += wb*c1.z; wc[15] += wb*c1.w;
            ws[0]  += wa*s0.x; ws[1]  += wa*s0.y; ws[2]  += wa*s0.z; ws[3]  += wa*s0.w;
            ws[4]  += wa*s1.x; ws[5]  += wa*s1.y; ws[6]  += wa*s1.z; ws[7]  += wa*s1.w;
            ws[8]  += wb*s0.x; ws[9]  += wb*s0.y; ws[10] += wb*s0.z; ws[11] += wb*s0.w;
            ws[12] += wb*s1.x; ws[13] += wb*s1.y; ws[14] += wb*s1.z; ws[15] += wb*s1.w;
        }
        /* all 4 K-groups write their partials */
        float* r = &sR[tid*SR_STRIDE];
        *(float4*)&r[0]  = make_float4(wc[0],  wc[1],  wc[2],  wc[3]);
        *(float4*)&r[4]  = make_float4(wc[4],  wc[5],  wc[6],  wc[7]);
        *(float4*)&r[8]  = make_float4(wc[8],  wc[9],  wc[10], wc[11]);
        *(float4*)&r[12] = make_float4(wc[12], wc[13], wc[14], wc[15]);
        *(float4*)&r[16] = make_float4(ws[0],  ws[1],  ws[2],  ws[3]);
        *(float4*)&r[20] = make_float4(ws[4],  ws[5],  ws[6],  ws[7]);
        *(float4*)&r[24] = make_float4(ws[8],  ws[9],  ws[10], ws[11]);
        *(float4*)&r[28] = make_float4(ws[12], ws[13], ws[14], ws[15]);
    }
    __syncthreads();

    /* ---- reduce + elementwise: ALL 256 threads, 4 cols each ---- */
    {
        int row = tid >> 3, cg = tid & 7;
        int wr = ((row >> 1) << 2) + (cg >> 1);          /* writer id 0..63 */
        int ib = ((row & 1) << 3) + ((cg & 1) << 2);     /* offset in writer regs */
        float wc4[4] = {0.f, 0.f, 0.f, 0.f};
        float ws4[4] = {0.f, 0.f, 0.f, 0.f};
#pragma unroll
        for (int ks = 0; ks < 4; ks++) {
            const float* r = &sR[(ks*64 + wr)*SR_STRIDE];
#pragma unroll
            for (int j = 0; j < 4; j++) {
                wc4[j] += r[ib + j];
                ws4[j] += r[16 + ib + j];
            }
        }

        int g = (r0+row)*NN + n0 + cg*4;
        float4 fc = *(const float4*)&g_fc[g];
        float4 fs = *(const float4*)&g_fs[g];
        float ce[4] = {fc.x, fc.y, fc.z, fc.w};
        float se[4] = {fs.x, fs.y, fs.z, fs.w};
        float kv[4];
#pragma unroll
        for (int j = 0; j < 4; j++)
            /* k = sin*wc - cos*ws + (sAnc*cos - cAnc*sin) */
            kv[j] = fmaf(se[j], wc4[j] - cAnc, ce[j] * (sAnc - ws4[j]));

        float phiN[4];
        if (sub == 0) {
            *(float4*)&g_acc[g] = make_float4(kv[0], kv[1], kv[2], kv[3]);
            float4 p0 = *(const float4*)&g_phi[g];
            float ph[4] = {p0.x, p0.y, p0.z, p0.w};
#pragma unroll
            for (int j = 0; j < 4; j++) phiN[j] = fmaf(cNext, kv[j], ph[j]);
        } else if (sub == 3) {
            float4 a0 = *(const float4*)&g_acc[g];
            float av[4] = {a0.x, a0.y, a0.z, a0.w};
            float4 p0 = *(const float4*)&g_phi[g];
            float ph[4] = {p0.x, p0.y, p0.z, p0.w};
#pragma unroll
            for (int j = 0; j < 4; j++)
                phiN[j] = fmaf(DT/6.0f, av[j] + kv[j], ph[j]);
            *(float4*)&g_phi[g] = make_float4(phiN[0], phiN[1], phiN[2], phiN[3]);
        } else {
            float4 a0 = *(const float4*)&g_acc[g];
            float av[4] = {a0.x, a0.y, a0.z, a0.w};
#pragma unroll
            for (int j = 0; j < 4; j++) av[j] = fmaf(2.0f, kv[j], av[j]);
            *(float4*)&g_acc[g] = make_float4(av[0], av[1], av[2], av[3]);
            float4 p0 = *(const float4*)&g_phi[g];
            float ph[4] = {p0.x, p0.y, p0.z, p0.w};
#pragma unroll
            for (int j = 0; j < 4; j++) phiN[j] = fmaf(cNext, kv[j], ph[j]);
        }

        if (doTail) {
            float cn[4], sn[4];
#pragma unroll
            for (int j = 0; j < 4; j++) {
                __sincosf(phiN[j], &sn[j], &cn[j]);
                sC[row*SC_STRIDE + cg*4 + j] = cn[j];
                sS[row*SC_STRIDE + cg*4 + j] = sn[j];
            }
            *(float4*)&g_fc[g] = make_float4(cn[0], cn[1], cn[2], cn[3]);
            *(float4*)&g_fs[g] = make_float4(sn[0], sn[1], sn[2], sn[3]);
        }
    }

    /* ---- tail: next-eval features -> partial m (all 256 threads) ---- */
    if (doTail) {
        __syncthreads();
        m_tail(sC, sS, sXC, sXS, g_m[bufW], r0);
    }
}

/* ================= readout: [cos(phi), sin(phi)] @ Wout^T + b =========== */
__global__ void k_readout(const float* __restrict__ Wout,
                          const float* __restrict__ bout,
                          float* __restrict__ out) {
    __shared__ float red[256];
    int b = blockIdx.x, tid = threadIdx.x;
    float acc[COUT];
#pragma unroll
    for (int c = 0; c < COUT; c++) acc[c] = 0.f;

#pragma unroll
    for (int it = 0; it < 4; it++) {
        int n = tid + it*256;
        float phi = g_phi[b*NN + n];
        float s, c;
        sincosf(phi, &s, &c);     /* accurate: feeds output directly */
#pragma unroll
        for (int cls = 0; cls < COUT; cls++)
            acc[cls] += c*Wout[cls*(2*NN) + n] + s*Wout[cls*(2*NN) + NN + n];
    }
    for (int cls = 0; cls < COUT; cls++) {
        red[tid] = acc[cls];
        __syncthreads();
        for (int off = 128; off > 0; off >>= 1) {
            if (tid < off) red[tid] += red[tid + off];
            __syncthreads();
        }
        if (tid == 0) out[b*COUT + cls] = red[0] + bout[cls];
        __syncthreads();
    }
}

/* ================= host ================================================= */
extern "C" void kernel_launch(void* const* d_in, const int* in_sizes, int n_in,
                              void* d_out, int out_size) {
    (void)in_sizes; (void)n_in; (void)out_size;
    const float* x    = (const float*)d_in[0];
    const float* Wenc = (const float*)d_in[1];
    const float* benc = (const float*)d_in[2];
    const float* xi   = (const float*)d_in[3];
    const float* Wout = (const float*)d_in[4];
    const float* bout = (const float*)d_in[5];
    float* out = (float*)d_out;

    cudaFuncSetAttribute(k_encoder, cudaFuncAttributeMaxDynamicSharedMemorySize, SMEM_BYTES);
    cudaFuncSetAttribute(k_F,       cudaFuncAttributeMaxDynamicSharedMemorySize, SMEM_BYTES);

    k_init<<<512, 256>>>(xi);

    dim3 grid(NN/CH, 8);             /* 32 x 8 = 256 CTAs */
    k_encoder<<<grid, 256, SMEM_BYTES>>>(x, Wenc, benc);

    for (int e = 0; e < 64; e++) {
        int step = e >> 2, sub = e & 3;
        float t0 = (float)step * DT;
        float tE = (sub == 0) ? t0 : ((sub == 3) ? t0 + DT : t0 + 0.5f*DT);
        float cNext = (sub == 2) ? DT : 0.5f*DT;
        /* anchor phase: fp32 arg rounding to match reference, accurate sin */
        float argf = OME * tE;
        double sa = sin((double)argf), ca = cos((double)argf);
        float sAnc = (float)((double)A_ANC * sa);
        float cAnc = (float)((double)A_ANC * ca);
        int bufR = e % 3, bufW = (e + 1) % 3, bufZ = (e + 2) % 3;
        int doTail = (e < 63) ? 1 : 0;
        k_F<<<grid, 256, SMEM_BYTES>>>(sub, sAnc, cAnc, cNext,
                                       bufR, bufW, bufZ, doTail);
    }

    k_readout<<<BATCH, 256>>>(Wout, bout, out);
}

// round 7
// speedup vs baseline: 2.6182x; 1.0493x over previous
#include <cuda_runtime.h>
#include <math.h>

#define BATCH 256
#define NN    1024
#define PP    128
#define DIN   784
#define COUT  10
#define CH    32                     /* columns per CTA */

#define TWO_PI_F 6.283185307179586f
#define DT       0.03125f            /* T/N_STEPS = 0.5/16, exact in fp32 */
#define BETA_N   (2.0f/1024.0f)
#define A_ANC    0.08f
#define OME      (TWO_PI_F*200.0f)

typedef unsigned long long ull;

__device__ __forceinline__ ull pack2(float a, float b) {
    ull r; asm("mov.b64 %0,{%1,%2};" : "=l"(r) : "f"(a), "f"(b)); return r;
}
__device__ __forceinline__ ull fma2(ull a, ull b, ull c) {
    ull d; asm("fma.rn.f32x2 %0,%1,%2,%3;" : "=l"(d) : "l"(a), "l"(b), "l"(c));
    return d;
}

/* ---- device scratch (static globals; no allocation allowed) ---- */
__device__ float g_xc[PP*NN];       /* cos(xi) [p][n] */
__device__ float g_xs[PP*NN];       /* sin(xi) [p][n] */
__device__ float g_phi[BATCH*NN];   /* base state */
__device__ float g_fc[BATCH*NN];    /* cos(phi_eval) features */
__device__ float g_fs[BATCH*NN];    /* sin(phi_eval) features */
__device__ float g_acc[BATCH*NN];   /* RK4 accumulator */
__device__ float g_m[3][BATCH*PP];  /* rotating overlap buffers */

/* ---- shared layout (floats) ---- */
#define SW_STRIDE 130                /* w tile [32][130] */
#define SX_STRIDE 36                 /* xc/xs tiles [128][36] */
#define SC_STRIDE 36                 /* c/s tiles [32][36] */
#define SR_STRIDE 36                 /* reduction: 256 writers x 36 */
#define SW_FLOATS (32*SW_STRIDE)     /* 4160 */
#define SX_FLOATS (128*SX_STRIDE)    /* 4608 */
#define SC_FLOATS (32*SC_STRIDE)     /* 1152 */
#define SR_FLOATS (256*SR_STRIDE)    /* 9216 */
#define SMEM_FLOATS (SW_FLOATS + 2*SX_FLOATS + 2*SC_FLOATS + SR_FLOATS)
#define SMEM_BYTES  (SMEM_FLOATS*4)  /* 99584 bytes -> 2 CTAs/SM */

/* ================= init: cos/sin of xi + zero first two m buffers ======= */
__global__ void k_init(const float* __restrict__ xi) {
    int i = blockIdx.x*256 + threadIdx.x;
    if (i < PP*NN) {
        float v = xi[i];
        g_xc[i] = cosf(v);
        g_xs[i] = sinf(v);
    }
    if (i < BATCH*PP) { g_m[0][i] = 0.f; g_m[1][i] = 0.f; }
}

/* load xc/xs tiles [128 p][32 n] for column chunk n0 into shared */
__device__ __forceinline__ void load_xtiles(float* sXC, float* sXS, int n0) {
    for (int i = threadIdx.x; i < 128*8; i += 256) {
        int p = i >> 3, q = (i & 7) << 2;
        float4 a = *(const float4*)&g_xc[p*NN + n0 + q];
        *(float4*)&sXC[p*SX_STRIDE + q] = a;
        float4 b = *(const float4*)&g_xs[p*NN + n0 + q];
        *(float4*)&sXS[p*SX_STRIDE + q] = b;
    }
}

/* partial m over this CTA's 32-col chunk, atomicAdd into mbuf.
   Tile: 8 rows x 4 patterns per thread-pair, n split in 2 halves of 16;
   halves combined via shfl_xor(16); lanes with ns==0 issue the atomics.
   tile = warp*16 + (lane&15): rowg = tile>>5 (8 rows), pg = tile&31,
   patterns p = pg + 32*pp. */
__device__ __forceinline__ void m_tail(const float* sC, const float* sS,
                                       const float* sXC, const float* sXS,
                                       float* mbuf, int r0) {
    int t = threadIdx.x;
    int w = t >> 5, l = t & 31;
    int ns   = l >> 4;               /* n half: 0/1 */
    int tile = w*16 + (l & 15);      /* 0..127 */
    int rowg = tile >> 5;            /* 0..3  -> rows rowg*8.. */
    int pg   = tile & 31;            /* 0..31 -> pats pg + 32*pp */
    float acc[32];
#pragma unroll
    for (int i = 0; i < 32; i++) acc[i] = 0.f;
    const float* cB  = sC  + (rowg*8)*SC_STRIDE + ns*16;
    const float* sB  = sS  + (rowg*8)*SC_STRIDE + ns*16;
    const float* xcB = sXC + pg*SX_STRIDE + ns*16;
    const float* xsB = sXS + pg*SX_STRIDE + ns*16;
#pragma unroll
    for (int nn = 0; nn < 16; nn += 4) {
        float4 cr[8], sr[8];
#pragma unroll
        for (int r = 0; r < 8; r++) {
            cr[r] = *(const float4*)&cB[r*SC_STRIDE + nn];
            sr[r] = *(const float4*)&sB[r*SC_STRIDE + nn];
        }
#pragma unroll
        for (int pp = 0; pp < 4; pp++) {
            float4 xc4 = *(const float4*)&xcB[pp*32*SX_STRIDE + nn];
            float4 xs4 = *(const float4*)&xsB[pp*32*SX_STRIDE + nn];
#pragma unroll
            for (int r = 0; r < 8; r++) {
                float v = acc[pp*8 + r];
                v = fmaf(cr[r].x, xc4.x, v); v = fmaf(sr[r].x, xs4.x, v);
                v = fmaf(cr[r].y, xc4.y, v); v = fmaf(sr[r].y, xs4.y, v);
                v = fmaf(cr[r].z, xc4.z, v); v = fmaf(sr[r].z, xs4.z, v);
                v = fmaf(cr[r].w, xc4.w, v); v = fmaf(sr[r].w, xs4.w, v);
                acc[pp*8 + r] = v;
            }
        }
    }
#pragma unroll
    for (int i = 0; i < 32; i++)
        acc[i] += __shfl_xor_sync(0xffffffffu, acc[i], 16);
    if (ns == 0) {
#pragma unroll
        for (int pp = 0; pp < 4; pp++)
#pragma unroll
            for (int r = 0; r < 8; r++)
                atomicAdd(&mbuf[(r0 + rowg*8 + r)*PP + pg + 32*pp],
                          acc[pp*8 + r]);
    }
}

/* ================= encoder: phi0 = 2pi*sigmoid(x @ Wenc^T + b), + m0 ==== */
__global__ void __launch_bounds__(256, 2)
k_encoder(const float* __restrict__ x,
          const float* __restrict__ Wenc,
          const float* __restrict__ benc) {
    extern __shared__ float sm[];
    float* sA  = sm;                 /* [32][17] staging, aliases sW region */
    float* sB  = sm + 32*17;         /* [32][17] */
    float* sXC = sm + SW_FLOATS;
    float* sXS = sXC + SX_FLOATS;
    float* sC  = sXS + SX_FLOATS;
    float* sS  = sC + SC_FLOATS;

    int n0 = blockIdx.x*CH, r0 = blockIdx.y*32;
    int tid = threadIdx.x;
    int row = tid >> 3, ng = tid & 7, nb = ng*4;

    float acc[4];
#pragma unroll
    for (int i = 0; i < 4; i++) acc[i] = 0.f;

    for (int d0 = 0; d0 < DIN; d0 += 16) {
        for (int i = tid; i < 512; i += 256) {
            int r = i >> 4, j = i & 15;
            sA[r*17 + j] = x[(r0+r)*DIN + d0 + j];
            sB[r*17 + j] = Wenc[(n0+r)*DIN + d0 + j];
        }
        __syncthreads();
#pragma unroll
        for (int j = 0; j < 16; j++) {
            float xa = sA[row*17 + j];
#pragma unroll
            for (int i = 0; i < 4; i++) acc[i] += xa * sB[(nb+i)*17 + j];
        }
        __syncthreads();
    }

    load_xtiles(sXC, sXS, n0);

#pragma unroll
    for (int i = 0; i < 4; i++) {
        float z  = acc[i] + benc[n0 + nb + i];
        float p0 = TWO_PI_F / (1.0f + expf(-z));
        int gi = (r0+row)*NN + n0 + nb + i;
        g_phi[gi]  = p0;
        float ss, cc;
        __sincosf(p0, &ss, &cc);
        g_fc[gi] = cc;
        g_fs[gi] = ss;
        sC[row*SC_STRIDE + nb + i] = cc;
        sS[row*SC_STRIDE + nb + i] = ss;
    }
    __syncthreads();
    m_tail(sC, sS, sXC, sXS, g_m[0], r0);
}

/* ================= fused per-eval kernel ================================ */
__global__ void __launch_bounds__(256, 2)
k_F(int sub, float sAnc, float cAnc, float cNext,
    int bufR, int bufW, int bufZ, int doTail) {
    extern __shared__ float sm[];
    float* sW  = sm;
    float* sXC = sm + SW_FLOATS;
    float* sXS = sXC + SX_FLOATS;
    float* sC  = sXS + SX_FLOATS;
    float* sS  = sC + SC_FLOATS;
    float* sR  = sS + SC_FLOATS;

    int n0 = blockIdx.x*CH, r0 = blockIdx.y*32;
    int tid = threadIdx.x;

    /* zero this CTA's slice of the buffer used two evals ahead */
    {
        int cta = blockIdx.y*32 + blockIdx.x;          /* 0..255 */
        if (tid < 128) g_m[bufZ][cta*128 + tid] = 0.f;
    }

    /* ---- P0: softmax over 128 patterns (arg in [-2,2]: no max shift) ---- */
    {
        int row = tid >> 3, l8 = tid & 7;
        const float* mrow = &g_m[bufR][(r0+row)*PP];
        float a[16];
        float ssum = 0.f;
#pragma unroll
        for (int j = 0; j < 16; j++) {
            a[j] = __expf(mrow[l8 + (j << 3)] * BETA_N);
            ssum += a[j];
        }
#pragma unroll
        for (int w = 1; w < 8; w <<= 1)
            ssum += __shfl_xor_sync(0xffffffffu, ssum, w);
        float inv = 1.0f / ssum;
#pragma unroll
        for (int j = 0; j < 16; j++)
            sW[row*SW_STRIDE + l8 + (j << 3)] = a[j] * inv;
    }

    load_xtiles(sXC, sXS, n0);
    __syncthreads();

    /* ---- P2: coupling GEMM, tile 4 rows x 4 cols (f32x2), K-split 4 ----
       ks = tid>>6, rowg = (tid>>3)&7 (4 rows each), colg = tid&7 (4 cols) */
    {
        int ks   = tid >> 6;
        int r6   = tid & 63;
        int rowg = r6 >> 3;
        int colg = r6 & 7;
        ull aC0[4], aC1[4], aS0[4], aS1[4];
#pragma unroll
        for (int i = 0; i < 4; i++) { aC0[i]=0ull; aC1[i]=0ull; aS0[i]=0ull; aS1[i]=0ull; }
        const float* wB  = &sW[(rowg*4)*SW_STRIDE + ks*32];
        const float* xcB = &sXC[(ks*32)*SX_STRIDE + colg*4];
        const float* xsB = &sXS[(ks*32)*SX_STRIDE + colg*4];
#pragma unroll 4
        for (int p = 0; p < 32; p++) {
            ulonglong2 cp = *(const ulonglong2*)&xcB[p*SX_STRIDE];
            ulonglong2 sp = *(const ulonglong2*)&xsB[p*SX_STRIDE];
#pragma unroll
            for (int i = 0; i < 4; i++) {
                float wv = wB[i*SW_STRIDE + p];
                ull wp = pack2(wv, wv);
                aC0[i] = fma2(wp, cp.x, aC0[i]);
                aC1[i] = fma2(wp, cp.y, aC1[i]);
                aS0[i] = fma2(wp, sp.x, aS0[i]);
                aS1[i] = fma2(wp, sp.y, aS1[i]);
            }
        }
        /* layout: floats [0..15] = wc rows 0..3 (4 each), [16..31] = ws */
        float* rr = &sR[tid*SR_STRIDE];
#pragma unroll
        for (int i = 0; i < 4; i++) {
            *(ull*)&rr[i*4]        = aC0[i];
            *(ull*)&rr[i*4 + 2]    = aC1[i];
            *(ull*)&rr[16 + i*4]   = aS0[i];
            *(ull*)&rr[16 + i*4+2] = aS1[i];
        }
    }
    __syncthreads();

    /* ---- reduce + elementwise: ALL 256 threads, 4 cols each ---- */
    {
        int row = tid >> 3, cf = tid & 7;
        int wr = ((row >> 2) << 3) + cf;     /* writer id 0..63 */
        int ib = (row & 3) * 4;              /* offset in writer's 16 floats */
        float wc4[4] = {0.f, 0.f, 0.f, 0.f};
        float ws4[4] = {0.f, 0.f, 0.f, 0.f};
#pragma unroll
        for (int ksr = 0; ksr < 4; ksr++) {
            const float* r = &sR[(ksr*64 + wr)*SR_STRIDE];
            float4 c4 = *(const float4*)&r[ib];
            float4 s4 = *(const float4*)&r[16 + ib];
            wc4[0] += c4.x; wc4[1] += c4.y; wc4[2] += c4.z; wc4[3] += c4.w;
            ws4[0] += s4.x; ws4[1] += s4.y; ws4[2] += s4.z; ws4[3] += s4.w;
        }

        int g = (r0+row)*NN + n0 + cf*4;
        float4 fc = *(const float4*)&g_fc[g];
        float4 fs = *(const float4*)&g_fs[g];
        float ce[4] = {fc.x, fc.y, fc.z, fc.w};
        float se[4] = {fs.x, fs.y, fs.z, fs.w};
        float kv[4];
#pragma unroll
        for (int j = 0; j < 4; j++)
            /* k = sin*wc - cos*ws + (sAnc*cos - cAnc*sin) */
            kv[j] = fmaf(se[j], wc4[j] - cAnc, ce[j] * (sAnc - ws4[j]));

        float phiN[4];
        if (sub == 0) {
            *(float4*)&g_acc[g] = make_float4(kv[0], kv[1], kv[2], kv[3]);
            float4 p0 = *(const float4*)&g_phi[g];
            float ph[4] = {p0.x, p0.y, p0.z, p0.w};
#pragma unroll
            for (int j = 0; j < 4; j++) phiN[j] = fmaf(cNext, kv[j], ph[j]);
        } else if (sub == 3) {
            float4 a0 = *(const float4*)&g_acc[g];
            float av[4] = {a0.x, a0.y, a0.z, a0.w};
            float4 p0 = *(const float4*)&g_phi[g];
            float ph[4] = {p0.x, p0.y, p0.z, p0.w};
#pragma unroll
            for (int j = 0; j < 4; j++)
                phiN[j] = fmaf(DT/6.0f, av[j] + kv[j], ph[j]);
            *(float4*)&g_phi[g] = make_float4(phiN[0], phiN[1], phiN[2], phiN[3]);
        } else {
            float4 a0 = *(const float4*)&g_acc[g];
            float av[4] = {a0.x, a0.y, a0.z, a0.w};
#pragma unroll
            for (int j = 0; j < 4; j++) av[j] = fmaf(2.0f, kv[j], av[j]);
            *(float4*)&g_acc[g] = make_float4(av[0], av[1], av[2], av[3]);
            float4 p0 = *(const float4*)&g_phi[g];
            float ph[4] = {p0.x, p0.y, p0.z, p0.w};
#pragma unroll
            for (int j = 0; j < 4; j++) phiN[j] = fmaf(cNext, kv[j], ph[j]);
        }

        if (doTail) {
            float cn[4], sn[4];
#pragma unroll
            for (int j = 0; j < 4; j++) {
                __sincosf(phiN[j], &sn[j], &cn[j]);
                sC[row*SC_STRIDE + cf*4 + j] = cn[j];
                sS[row*SC_STRIDE + cf*4 + j] = sn[j];
            }
            *(float4*)&g_fc[g] = make_float4(cn[0], cn[1], cn[2], cn[3]);
            *(float4*)&g_fs[g] = make_float4(sn[0], sn[1], sn[2], sn[3]);
        }
    }

    /* ---- tail: next-eval features -> partial m (all 256 threads) ---- */
    if (doTail) {
        __syncthreads();
        m_tail(sC, sS, sXC, sXS, g_m[bufW], r0);
    }
}

/* ================= readout: [cos(phi), sin(phi)] @ Wout^T + b =========== */
__global__ void k_readout(const float* __restrict__ Wout,
                          const float* __restrict__ bout,
                          float* __restrict__ out) {
    __shared__ float red[256];
    int b = blockIdx.x, tid = threadIdx.x;
    float acc[COUT];
#pragma unroll
    for (int c = 0; c < COUT; c++) acc[c] = 0.f;

#pragma unroll
    for (int it = 0; it < 4; it++) {
        int n = tid + it*256;
        float phi = g_phi[b*NN + n];
        float s, c;
        sincosf(phi, &s, &c);     /* accurate: feeds output directly */
#pragma unroll
        for (int cls = 0; cls < COUT; cls++)
            acc[cls] += c*Wout[cls*(2*NN) + n] + s*Wout[cls*(2*NN) + NN + n];
    }
    for (int cls = 0; cls < COUT; cls++) {
        red[tid] = acc[cls];
        __syncthreads();
        for (int off = 128; off > 0; off >>= 1) {
            if (tid < off) red[tid] += red[tid + off];
            __syncthreads();
        }
        if (tid == 0) out[b*COUT + cls] = red[0] + bout[cls];
        __syncthreads();
    }
}

/* ================= host ================================================= */
extern "C" void kernel_launch(void* const* d_in, const int* in_sizes, int n_in,
                              void* d_out, int out_size) {
    (void)in_sizes; (void)n_in; (void)out_size;
    const float* x    = (const float*)d_in[0];
    const float* Wenc = (const float*)d_in[1];
    const float* benc = (const float*)d_in[2];
    const float* xi   = (const float*)d_in[3];
    const float* Wout = (const float*)d_in[4];
    const float* bout = (const float*)d_in[5];
    float* out = (float*)d_out;

    cudaFuncSetAttribute(k_encoder, cudaFuncAttributeMaxDynamicSharedMemorySize, SMEM_BYTES);
    cudaFuncSetAttribute(k_F,       cudaFuncAttributeMaxDynamicSharedMemorySize, SMEM_BYTES);

    k_init<<<512, 256>>>(xi);

    dim3 grid(NN/CH, 8);             /* 32 x 8 = 256 CTAs */
    k_encoder<<<grid, 256, SMEM_BYTES>>>(x, Wenc, benc);

    for (int e = 0; e < 64; e++) {
        int step = e >> 2, sub = e & 3;
        float t0 = (float)step * DT;
        float tE = (sub == 0) ? t0 : ((sub == 3) ? t0 + DT : t0 + 0.5f*DT);
        float cNext = (sub == 2) ? DT : 0.5f*DT;
        /* anchor phase: fp32 arg rounding to match reference, accurate sin */
        float argf = OME * tE;
        double sa = sin((double)argf), ca = cos((double)argf);
        float sAnc = (float)((double)A_ANC * sa);
        float cAnc = (float)((double)A_ANC * ca);
        int bufR = e % 3, bufW = (e + 1) % 3, bufZ = (e + 2) % 3;
        int doTail = (e < 63) ? 1 : 0;
        k_F<<<grid, 256, SMEM_BYTES>>>(sub, sAnc, cAnc, cNext,
                                       bufR, bufW, bufZ, doTail);
    }

    k_readout<<<BATCH, 256>>>(Wout, bout, out);
}

// round 8
// speedup vs baseline: 2.6716x; 1.0204x over previous
#include <cuda_runtime.h>
#include <math.h>

#define BATCH 256
#define NN    1024
#define PP    128
#define DIN   784
#define COUT  10
#define CH    32                     /* columns per CTA */

#define TWO_PI_F 6.283185307179586f
#define DT       0.03125f            /* T/N_STEPS = 0.5/16, exact in fp32 */
#define BETA_N   (2.0f/1024.0f)
#define A_ANC    0.08f
#define OME      (TWO_PI_F*200.0f)

typedef unsigned long long ull;

__device__ __forceinline__ ull pack2(float a, float b) {
    ull r; asm("mov.b64 %0,{%1,%2};" : "=l"(r) : "f"(a), "f"(b)); return r;
}
__device__ __forceinline__ ull fma2(ull a, ull b, ull c) {
    ull d; asm("fma.rn.f32x2 %0,%1,%2,%3;" : "=l"(d) : "l"(a), "l"(b), "l"(c));
    return d;
}
__device__ __forceinline__ unsigned su32(const void* p) {
    return (unsigned)__cvta_generic_to_shared(p);
}
#define CP16(dst, src) \
    asm volatile("cp.async.cg.shared.global [%0], [%1], 16;" :: "r"(dst), "l"(src))
#define CP_COMMIT() asm volatile("cp.async.commit_group;")
#define CP_WAIT(n)  asm volatile("cp.async.wait_group %0;" :: "n"(n))

/* ---- device scratch (static globals; no allocation allowed) ---- */
__device__ float g_xc[PP*NN];       /* cos(xi) [p][n] */
__device__ float g_xs[PP*NN];       /* sin(xi) [p][n] */
__device__ float g_phi[BATCH*NN];   /* base state */
__device__ float g_fc[BATCH*NN];    /* cos(phi_eval) features */
__device__ float g_fs[BATCH*NN];    /* sin(phi_eval) features */
__device__ float g_acc[BATCH*NN];   /* RK4 accumulator */
__device__ float g_m[3][BATCH*PP];  /* rotating overlap buffers */

/* ---- shared layout (floats) ---- */
#define SW_STRIDE 130                /* w tile [32][130] */
#define SX_STRIDE 36                 /* xc/xs tiles [128][36] */
#define SC_STRIDE 36                 /* c/s/phi/acc tiles [32][36] */
#define SR_STRIDE 36                 /* reduction: 256 writers x 36 */
#define SW_FLOATS (32*SW_STRIDE)     /* 4160 */
#define SX_FLOATS (128*SX_STRIDE)    /* 4608 */
#define SC_FLOATS (32*SC_STRIDE)     /* 1152 */
#define SR_FLOATS (256*SR_STRIDE)    /* 9216; first 4096 alias m-prefetch */
#define SMEM_FLOATS (SW_FLOATS + 2*SX_FLOATS + 4*SC_FLOATS + SR_FLOATS)
#define SMEM_BYTES  (SMEM_FLOATS*4)  /* 108800 bytes -> 2 CTAs/SM */

/* ================= init: cos/sin of xi + zero first two m buffers ======= */
__global__ void k_init(const float* __restrict__ xi) {
    int i = blockIdx.x*256 + threadIdx.x;
    if (i < PP*NN) {
        float v = xi[i];
        g_xc[i] = cosf(v);
        g_xs[i] = sinf(v);
    }
    if (i < BATCH*PP) { g_m[0][i] = 0.f; g_m[1][i] = 0.f; }
}

/* load xc/xs tiles [128 p][32 n] for column chunk n0 into shared (LDG path,
   used by encoder only) */
__device__ __forceinline__ void load_xtiles(float* sXC, float* sXS, int n0) {
    for (int i = threadIdx.x; i < 128*8; i += 256) {
        int p = i >> 3, q = (i & 7) << 2;
        float4 a = *(const float4*)&g_xc[p*NN + n0 + q];
        *(float4*)&sXC[p*SX_STRIDE + q] = a;
        float4 b = *(const float4*)&g_xs[p*NN + n0 + q];
        *(float4*)&sXS[p*SX_STRIDE + q] = b;
    }
}

/* partial m over this CTA's 32-col chunk, atomicAdd into mbuf.
   Tile: 8 rows x 4 patterns per thread-pair, n split in 2 halves of 16;
   halves combined via shfl_xor(16); lanes with ns==0 issue the atomics. */
__device__ __forceinline__ void m_tail(const float* sC, const float* sS,
                                       const float* sXC, const float* sXS,
                                       float* mbuf, int r0) {
    int t = threadIdx.x;
    int w = t >> 5, l = t & 31;
    int ns   = l >> 4;               /* n half: 0/1 */
    int tile = w*16 + (l & 15);      /* 0..127 */
    int rowg = tile >> 5;            /* 0..3  -> rows rowg*8.. */
    int pg   = tile & 31;            /* 0..31 -> pats pg + 32*pp */
    float acc[32];
#pragma unroll
    for (int i = 0; i < 32; i++) acc[i] = 0.f;
    const float* cB  = sC  + (rowg*8)*SC_STRIDE + ns*16;
    const float* sB  = sS  + (rowg*8)*SC_STRIDE + ns*16;
    const float* xcB = sXC + pg*SX_STRIDE + ns*16;
    const float* xsB = sXS + pg*SX_STRIDE + ns*16;
#pragma unroll
    for (int nn = 0; nn < 16; nn += 4) {
        float4 cr[8], sr[8];
#pragma unroll
        for (int r = 0; r < 8; r++) {
            cr[r] = *(const float4*)&cB[r*SC_STRIDE + nn];
            sr[r] = *(const float4*)&sB[r*SC_STRIDE + nn];
        }
#pragma unroll
        for (int pp = 0; pp < 4; pp++) {
            float4 xc4 = *(const float4*)&xcB[pp*32*SX_STRIDE + nn];
            float4 xs4 = *(const float4*)&xsB[pp*32*SX_STRIDE + nn];
#pragma unroll
            for (int r = 0; r < 8; r++) {
                float v = acc[pp*8 + r];
                v = fmaf(cr[r].x, xc4.x, v); v = fmaf(sr[r].x, xs4.x, v);
                v = fmaf(cr[r].y, xc4.y, v); v = fmaf(sr[r].y, xs4.y, v);
                v = fmaf(cr[r].z, xc4.z, v); v = fmaf(sr[r].z, xs4.z, v);
                v = fmaf(cr[r].w, xc4.w, v); v = fmaf(sr[r].w, xs4.w, v);
                acc[pp*8 + r] = v;
            }
        }
    }
#pragma unroll
    for (int i = 0; i < 32; i++)
        acc[i] += __shfl_xor_sync(0xffffffffu, acc[i], 16);
    if (ns == 0) {
#pragma unroll
        for (int pp = 0; pp < 4; pp++)
#pragma unroll
            for (int r = 0; r < 8; r++)
                atomicAdd(&mbuf[(r0 + rowg*8 + r)*PP + pg + 32*pp],
                          acc[pp*8 + r]);
    }
}

/* ================= encoder: phi0 = 2pi*sigmoid(x @ Wenc^T + b), + m0 ==== */
__global__ void __launch_bounds__(256, 2)
k_encoder(const float* __restrict__ x,
          const float* __restrict__ Wenc,
          const float* __restrict__ benc) {
    extern __shared__ float sm[];
    float* sA  = sm;                 /* [32][17] staging, aliases sW region */
    float* sB  = sm + 32*17;         /* [32][17] */
    float* sXC = sm + SW_FLOATS;
    float* sXS = sXC + SX_FLOATS;
    float* sC  = sXS + SX_FLOATS;
    float* sS  = sC + SC_FLOATS;

    int n0 = blockIdx.x*CH, r0 = blockIdx.y*32;
    int tid = threadIdx.x;
    int row = tid >> 3, ng = tid & 7, nb = ng*4;

    float acc[4];
#pragma unroll
    for (int i = 0; i < 4; i++) acc[i] = 0.f;

    for (int d0 = 0; d0 < DIN; d0 += 16) {
        for (int i = tid; i < 512; i += 256) {
            int r = i >> 4, j = i & 15;
            sA[r*17 + j] = x[(r0+r)*DIN + d0 + j];
            sB[r*17 + j] = Wenc[(n0+r)*DIN + d0 + j];
        }
        __syncthreads();
#pragma unroll
        for (int j = 0; j < 16; j++) {
            float xa = sA[row*17 + j];
#pragma unroll
            for (int i = 0; i < 4; i++) acc[i] += xa * sB[(nb+i)*17 + j];
        }
        __syncthreads();
    }

    load_xtiles(sXC, sXS, n0);

#pragma unroll
    for (int i = 0; i < 4; i++) {
        float z  = acc[i] + benc[n0 + nb + i];
        float p0 = TWO_PI_F / (1.0f + expf(-z));
        int gi = (r0+row)*NN + n0 + nb + i;
        g_phi[gi]  = p0;
        float ss, cc;
        __sincosf(p0, &ss, &cc);
        g_fc[gi] = cc;
        g_fs[gi] = ss;
        sC[row*SC_STRIDE + nb + i] = cc;
        sS[row*SC_STRIDE + nb + i] = ss;
    }
    __syncthreads();
    m_tail(sC, sS, sXC, sXS, g_m[0], r0);
}

/* ================= fused per-eval kernel ================================ */
__global__ void __launch_bounds__(256, 2)
k_F(int sub, float sAnc, float cAnc, float cNext,
    int bufR, int bufW, int bufZ, int doTail) {
    extern __shared__ float sm[];
    float* sW  = sm;
    float* sXC = sm + SW_FLOATS;
    float* sXS = sXC + SX_FLOATS;
    float* sC  = sXS + SX_FLOATS;      /* fc prefetch -> new cos features  */
    float* sS  = sC + SC_FLOATS;       /* fs prefetch -> new sin features  */
    float* sP  = sS + SC_FLOATS;       /* phi prefetch                     */
    float* sA  = sP + SC_FLOATS;       /* acc prefetch                     */
    float* sR  = sA + SC_FLOATS;       /* GEMM reduction; [0,4096) = m pre */

    int n0 = blockIdx.x*CH, r0 = blockIdx.y*32;
    int tid = threadIdx.x;
    int row = tid >> 3, cf = tid & 7;
    int so  = row*SC_STRIDE + cf*4;
    int gso = (r0+row)*NN + n0 + cf*4;

    /* ---- prefetch group 1: m slice (64 B/thread, self-consumed) ---- */
    {
        const float* gmp = &g_m[bufR][(r0+row)*PP + cf*16];
        unsigned d = su32(&sR[row*PP + cf*16]);
        CP16(d,      gmp);
        CP16(d + 16, gmp + 4);
        CP16(d + 32, gmp + 8);
        CP16(d + 48, gmp + 12);
    }
    CP_COMMIT();
    /* ---- prefetch group 2: xc/xs tiles ---- */
#pragma unroll
    for (int it = 0; it < 4; it++) {
        int i = tid + it*256;
        int p = i >> 3, q = (i & 7) << 2;
        CP16(su32(&sXC[p*SX_STRIDE + q]), &g_xc[p*NN + n0 + q]);
        CP16(su32(&sXS[p*SX_STRIDE + q]), &g_xs[p*NN + n0 + q]);
    }
    CP_COMMIT();
    /* ---- prefetch group 3: state (fc, fs, phi, acc) ---- */
    CP16(su32(&sC[so]), &g_fc[gso]);
    CP16(su32(&sS[so]), &g_fs[gso]);
    CP16(su32(&sP[so]), &g_phi[gso]);
    CP16(su32(&sA[so]), &g_acc[gso]);
    CP_COMMIT();

    /* zero this CTA's slice of the buffer used two evals ahead */
    {
        int cta = blockIdx.y*32 + blockIdx.x;
        if (tid < 128) g_m[bufZ][cta*128 + tid] = 0.f;
    }

    /* ---- P0: softmax over 128 patterns (arg in [-2,2]: no max shift) ----
       thread handles 16 contiguous patterns cf*16..cf*16+15 of its row   */
    CP_WAIT(2);
    {
        const float* mrow = &sR[row*PP + cf*16];
        float a[16];
        float ssum = 0.f;
#pragma unroll
        for (int j = 0; j < 16; j++) {
            a[j] = __expf(mrow[j] * BETA_N);
            ssum += a[j];
        }
#pragma unroll
        for (int w = 1; w < 8; w <<= 1)
            ssum += __shfl_xor_sync(0xffffffffu, ssum, w);
        float inv = 1.0f / ssum;
#pragma unroll
        for (int j = 0; j < 16; j++)
            sW[row*SW_STRIDE + cf*16 + j] = a[j] * inv;
    }
    CP_WAIT(1);
    __syncthreads();

    /* ---- P2: coupling GEMM, tile 4 rows x 4 cols (f32x2), K-split 4 ---- */
    {
        int ks   = tid >> 6;
        int r6   = tid & 63;
        int rowg = r6 >> 3;
        int colg = r6 & 7;
        ull aC0[4], aC1[4], aS0[4], aS1[4];
#pragma unroll
        for (int i = 0; i < 4; i++) { aC0[i]=0ull; aC1[i]=0ull; aS0[i]=0ull; aS1[i]=0ull; }
        const float* wB  = &sW[(rowg*4)*SW_STRIDE + ks*32];
        const float* xcB = &sXC[(ks*32)*SX_STRIDE + colg*4];
        const float* xsB = &sXS[(ks*32)*SX_STRIDE + colg*4];
#pragma unroll 4
        for (int p = 0; p < 32; p++) {
            ulonglong2 cp = *(const ulonglong2*)&xcB[p*SX_STRIDE];
            ulonglong2 sp = *(const ulonglong2*)&xsB[p*SX_STRIDE];
#pragma unroll
            for (int i = 0; i < 4; i++) {
                float wv = wB[i*SW_STRIDE + p];
                ull wp = pack2(wv, wv);
                aC0[i] = fma2(wp, cp.x, aC0[i]);
                aC1[i] = fma2(wp, cp.y, aC1[i]);
                aS0[i] = fma2(wp, sp.x, aS0[i]);
                aS1[i] = fma2(wp, sp.y, aS1[i]);
            }
        }
        float* rr = &sR[tid*SR_STRIDE];
#pragma unroll
        for (int i = 0; i < 4; i++) {
            *(ull*)&rr[i*4]        = aC0[i];
            *(ull*)&rr[i*4 + 2]    = aC1[i];
            *(ull*)&rr[16 + i*4]   = aS0[i];
            *(ull*)&rr[16 + i*4+2] = aS1[i];
        }
    }
    CP_WAIT(0);
    __syncthreads();

    /* ---- reduce + elementwise: ALL 256 threads, 4 cols each ---- */
    {
        int wr = ((row >> 2) << 3) + cf;     /* writer id 0..63 */
        int ib = (row & 3) * 4;              /* offset in writer's 16 floats */
        float wc4[4] = {0.f, 0.f, 0.f, 0.f};
        float ws4[4] = {0.f, 0.f, 0.f, 0.f};
#pragma unroll
        for (int ksr = 0; ksr < 4; ksr++) {
            const float* r = &sR[(ksr*64 + wr)*SR_STRIDE];
            float4 c4 = *(const float4*)&r[ib];
            float4 s4 = *(const float4*)&r[16 + ib];
            wc4[0] += c4.x; wc4[1] += c4.y; wc4[2] += c4.z; wc4[3] += c4.w;
            ws4[0] += s4.x; ws4[1] += s4.y; ws4[2] += s4.z; ws4[3] += s4.w;
        }

        float4 fc = *(const float4*)&sC[so];
        float4 fs = *(const float4*)&sS[so];
        float ce[4] = {fc.x, fc.y, fc.z, fc.w};
        float se[4] = {fs.x, fs.y, fs.z, fs.w};
        float kv[4];
#pragma unroll
        for (int j = 0; j < 4; j++)
            /* k = sin*wc - cos*ws + (sAnc*cos - cAnc*sin) */
            kv[j] = fmaf(se[j], wc4[j] - cAnc, ce[j] * (sAnc - ws4[j]));

        float4 p0 = *(const float4*)&sP[so];
        float ph[4] = {p0.x, p0.y, p0.z, p0.w};
        float phiN[4];
        if (sub == 0) {
            *(float4*)&g_acc[gso] = make_float4(kv[0], kv[1], kv[2], kv[3]);
#pragma unroll
            for (int j = 0; j < 4; j++) phiN[j] = fmaf(cNext, kv[j], ph[j]);
        } else if (sub == 3) {
            float4 a0 = *(const float4*)&sA[so];
            float av[4] = {a0.x, a0.y, a0.z, a0.w};
#pragma unroll
            for (int j = 0; j < 4; j++)
                phiN[j] = fmaf(DT/6.0f, av[j] + kv[j], ph[j]);
            *(float4*)&g_phi[gso] = make_float4(phiN[0], phiN[1], phiN[2], phiN[3]);
        } else {
            float4 a0 = *(const float4*)&sA[so];
            float av[4] = {a0.x, a0.y, a0.z, a0.w};
#pragma unroll
            for (int j = 0; j < 4; j++) av[j] = fmaf(2.0f, kv[j], av[j]);
            *(float4*)&g_acc[gso] = make_float4(av[0], av[1], av[2], av[3]);
#pragma unroll
            for (int j = 0; j < 4; j++) phiN[j] = fmaf(cNext, kv[j], ph[j]);
        }

        if (doTail) {
            float cn[4], sn[4];
#pragma unroll
            for (int j = 0; j < 4; j++) {
                __sincosf(phiN[j], &sn[j], &cn[j]);
            }
            /* in-place: overwrite fc/fs staging with next-eval features */
            *(float4*)&sC[so] = make_float4(cn[0], cn[1], cn[2], cn[3]);
            *(float4*)&sS[so] = make_float4(sn[0], sn[1], sn[2], sn[3]);
            *(float4*)&g_fc[gso] = make_float4(cn[0], cn[1], cn[2], cn[3]);
            *(float4*)&g_fs[gso] = make_float4(sn[0], sn[1], sn[2], sn[3]);
        }
    }

    /* ---- tail: next-eval features -> partial m (all 256 threads) ---- */
    if (doTail) {
        __syncthreads();
        m_tail(sC, sS, sXC, sXS, g_m[bufW], r0);
    }
}

/* ================= readout: [cos(phi), sin(phi)] @ Wout^T + b =========== */
__global__ void k_readout(const float* __restrict__ Wout,
                          const float* __restrict__ bout,
                          float* __restrict__ out) {
    __shared__ float red[256];
    int b = blockIdx.x, tid = threadIdx.x;
    float acc[COUT];
#pragma unroll
    for (int c = 0; c < COUT; c++) acc[c] = 0.f;

#pragma unroll
    for (int it = 0; it < 4; it++) {
        int n = tid + it*256;
        float phi = g_phi[b*NN + n];
        float s, c;
        sincosf(phi, &s, &c);     /* accurate: feeds output directly */
#pragma unroll
        for (int cls = 0; cls < COUT; cls++)
            acc[cls] += c*Wout[cls*(2*NN) + n] + s*Wout[cls*(2*NN) + NN + n];
    }
    for (int cls = 0; cls < COUT; cls++) {
        red[tid] = acc[cls];
        __syncthreads();
        for (int off = 128; off > 0; off >>= 1) {
            if (tid < off) red[tid] += red[tid + off];
            __syncthreads();
        }
        if (tid == 0) out[b*COUT + cls] = red[0] + bout[cls];
        __syncthreads();
    }
}

/* ================= host ================================================= */
extern "C" void kernel_launch(void* const* d_in, const int* in_sizes, int n_in,
                              void* d_out, int out_size) {
    (void)in_sizes; (void)n_in; (void)out_size;
    const float* x    = (const float*)d_in[0];
    const float* Wenc = (const float*)d_in[1];
    const float* benc = (const float*)d_in[2];
    const float* xi   = (const float*)d_in[3];
    const float* Wout = (const float*)d_in[4];
    const float* bout = (const float*)d_in[5];
    float* out = (float*)d_out;

    cudaFuncSetAttribute(k_encoder, cudaFuncAttributeMaxDynamicSharedMemorySize, SMEM_BYTES);
    cudaFuncSetAttribute(k_F,       cudaFuncAttributeMaxDynamicSharedMemorySize, SMEM_BYTES);

    k_init<<<512, 256>>>(xi);

    dim3 grid(NN/CH, 8);             /* 32 x 8 = 256 CTAs */
    k_encoder<<<grid, 256, SMEM_BYTES>>>(x, Wenc, benc);

    for (int e = 0; e < 64; e++) {
        int step = e >> 2, sub = e & 3;
        float t0 = (float)step * DT;
        float tE = (sub == 0) ? t0 : ((sub == 3) ? t0 + DT : t0 + 0.5f*DT);
        float cNext = (sub == 2) ? DT : 0.5f*DT;
        /* anchor phase: fp32 arg rounding to match reference, accurate sin */
        float argf = OME * tE;
        double sa = sin((double)argf), ca = cos((double)argf);
        float sAnc = (float)((double)A_ANC * sa);
        float cAnc = (float)((double)A_ANC * ca);
        int bufR = e % 3, bufW = (e + 1) % 3, bufZ = (e + 2) % 3;
        int doTail = (e < 63) ? 1 : 0;
        k_F<<<grid, 256, SMEM_BYTES>>>(sub, sAnc, cAnc, cNext,
                                       bufR, bufW, bufZ, doTail);
    }

    k_readout<<<BATCH, 256>>>(Wout, bout, out);
}

// round 9
// speedup vs baseline: 2.7200x; 1.0181x over previous
#include <cuda_runtime.h>
#include <math.h>

#define BATCH 256
#define NN    1024
#define PP    128
#define DIN   784
#define COUT  10
#define CH    32                     /* columns per CTA */
#define NEV   64                     /* RK4 evals */

#define TWO_PI_F 6.283185307179586f
#define DT       0.03125f            /* T/N_STEPS = 0.5/16, exact in fp32 */
#define BETA_N   (2.0f/1024.0f)
#define A_ANC    0.08f
#define OME      (TWO_PI_F*200.0f)

typedef unsigned long long ull;

__device__ __forceinline__ ull pack2(float a, float b) {
    ull r; asm("mov.b64 %0,{%1,%2};" : "=l"(r) : "f"(a), "f"(b)); return r;
}
__device__ __forceinline__ ull fma2(ull a, ull b, ull c) {
    ull d; asm("fma.rn.f32x2 %0,%1,%2,%3;" : "=l"(d) : "l"(a), "l"(b), "l"(c));
    return d;
}
__device__ __forceinline__ unsigned su32(const void* p) {
    return (unsigned)__cvta_generic_to_shared(p);
}
#define CP16(dst, src) \
    asm volatile("cp.async.cg.shared.global [%0], [%1], 16;" :: "r"(dst), "l"(src))
#define CP_COMMIT() asm volatile("cp.async.commit_group;")
#define CP_WAIT(n)  asm volatile("cp.async.wait_group %0;" :: "n"(n))

struct EvalConsts { float sA[NEV]; float cA[NEV]; float cN[NEV]; };

/* ---- device scratch (static globals; no allocation allowed) ---- */
__device__ float g_xc[PP*NN];       /* cos(xi) [p][n] */
__device__ float g_xs[PP*NN];       /* sin(xi) [p][n] */
__device__ float g_phi[BATCH*NN];   /* base state */
__device__ float g_fc[BATCH*NN];    /* cos(phi_eval) features (encoder out) */
__device__ float g_fs[BATCH*NN];    /* sin(phi_eval) features */
__device__ float g_m[3][BATCH*PP];  /* rotating overlap buffers */
__device__ unsigned g_cnt[NEV];     /* per-eval grid barrier counters */

/* ---- shared layout (floats) ---- */
#define SW_STRIDE 130                /* w tile [32][130] */
#define SX_STRIDE 36                 /* xc/xs tiles [128][36] */
#define SC_STRIDE 36                 /* c/s/phi/acc tiles [32][36] */
#define SR_STRIDE 36                 /* reduction: 256 writers x 36 */
#define SW_FLOATS (32*SW_STRIDE)     /* 4160 */
#define SX_FLOATS (128*SX_STRIDE)    /* 4608 */
#define SC_FLOATS (32*SC_STRIDE)     /* 1152 */
#define SR_FLOATS (256*SR_STRIDE)    /* 9216; first 4096 alias m-prefetch */
#define SMEM_FLOATS (SW_FLOATS + 2*SX_FLOATS + 4*SC_FLOATS + SR_FLOATS)
#define SMEM_BYTES  (SMEM_FLOATS*4)  /* 108800 bytes -> 2 CTAs/SM */

/* ================= init: cos/sin of xi, zero m bufs + barrier cnt ======= */
__global__ void k_init(const float* __restrict__ xi) {
    int i = blockIdx.x*256 + threadIdx.x;
    if (i < PP*NN) {
        float v = xi[i];
        g_xc[i] = cosf(v);
        g_xs[i] = sinf(v);
    }
    if (i < BATCH*PP) { g_m[0][i] = 0.f; g_m[1][i] = 0.f; }
    if (i < NEV) g_cnt[i] = 0u;
}

/* load xc/xs tiles [128 p][32 n] for column chunk n0 (LDG path, encoder) */
__device__ __forceinline__ void load_xtiles(float* sXC, float* sXS, int n0) {
    for (int i = threadIdx.x; i < 128*8; i += 256) {
        int p = i >> 3, q = (i & 7) << 2;
        float4 a = *(const float4*)&g_xc[p*NN + n0 + q];
        *(float4*)&sXC[p*SX_STRIDE + q] = a;
        float4 b = *(const float4*)&g_xs[p*NN + n0 + q];
        *(float4*)&sXS[p*SX_STRIDE + q] = b;
    }
}

/* partial m over this CTA's 32-col chunk, atomicAdd into mbuf. */
__device__ __forceinline__ void m_tail(const float* sC, const float* sS,
                                       const float* sXC, const float* sXS,
                                       float* mbuf, int r0) {
    int t = threadIdx.x;
    int w = t >> 5, l = t & 31;
    int ns   = l >> 4;               /* n half: 0/1 */
    int tile = w*16 + (l & 15);      /* 0..127 */
    int rowg = tile >> 5;            /* 0..3  -> rows rowg*8.. */
    int pg   = tile & 31;            /* 0..31 -> pats pg + 32*pp */
    float acc[32];
#pragma unroll
    for (int i = 0; i < 32; i++) acc[i] = 0.f;
    const float* cB  = sC  + (rowg*8)*SC_STRIDE + ns*16;
    const float* sB  = sS  + (rowg*8)*SC_STRIDE + ns*16;
    const float* xcB = sXC + pg*SX_STRIDE + ns*16;
    const float* xsB = sXS + pg*SX_STRIDE + ns*16;
#pragma unroll
    for (int nn = 0; nn < 16; nn += 4) {
        float4 cr[8], sr[8];
#pragma unroll
        for (int r = 0; r < 8; r++) {
            cr[r] = *(const float4*)&cB[r*SC_STRIDE + nn];
            sr[r] = *(const float4*)&sB[r*SC_STRIDE + nn];
        }
#pragma unroll
        for (int pp = 0; pp < 4; pp++) {
            float4 xc4 = *(const float4*)&xcB[pp*32*SX_STRIDE + nn];
            float4 xs4 = *(const float4*)&xsB[pp*32*SX_STRIDE + nn];
#pragma unroll
            for (int r = 0; r < 8; r++) {
                float v = acc[pp*8 + r];
                v = fmaf(cr[r].x, xc4.x, v); v = fmaf(sr[r].x, xs4.x, v);
                v = fmaf(cr[r].y, xc4.y, v); v = fmaf(sr[r].y, xs4.y, v);
                v = fmaf(cr[r].z, xc4.z, v); v = fmaf(sr[r].z, xs4.z, v);
                v = fmaf(cr[r].w, xc4.w, v); v = fmaf(sr[r].w, xs4.w, v);
                acc[pp*8 + r] = v;
            }
        }
    }
#pragma unroll
    for (int i = 0; i < 32; i++)
        acc[i] += __shfl_xor_sync(0xffffffffu, acc[i], 16);
    if (ns == 0) {
#pragma unroll
        for (int pp = 0; pp < 4; pp++)
#pragma unroll
            for (int r = 0; r < 8; r++)
                atomicAdd(&mbuf[(r0 + rowg*8 + r)*PP + pg + 32*pp],
                          acc[pp*8 + r]);
    }
}

/* ================= encoder: phi0 = 2pi*sigmoid(x @ Wenc^T + b), + m0 ==== */
__global__ void __launch_bounds__(256, 2)
k_encoder(const float* __restrict__ x,
          const float* __restrict__ Wenc,
          const float* __restrict__ benc) {
    extern __shared__ float sm[];
    float* sA  = sm;                 /* [32][17] staging, aliases sW region */
    float* sB  = sm + 32*17;         /* [32][17] */
    float* sXC = sm + SW_FLOATS;
    float* sXS = sXC + SX_FLOATS;
    float* sC  = sXS + SX_FLOATS;
    float* sS  = sC + SC_FLOATS;

    int n0 = blockIdx.x*CH, r0 = blockIdx.y*32;
    int tid = threadIdx.x;
    int row = tid >> 3, ng = tid & 7, nb = ng*4;

    float acc[4];
#pragma unroll
    for (int i = 0; i < 4; i++) acc[i] = 0.f;

    for (int d0 = 0; d0 < DIN; d0 += 16) {
        for (int i = tid; i < 512; i += 256) {
            int r = i >> 4, j = i & 15;
            sA[r*17 + j] = x[(r0+r)*DIN + d0 + j];
            sB[r*17 + j] = Wenc[(n0+r)*DIN + d0 + j];
        }
        __syncthreads();
#pragma unroll
        for (int j = 0; j < 16; j++) {
            float xa = sA[row*17 + j];
#pragma unroll
            for (int i = 0; i < 4; i++) acc[i] += xa * sB[(nb+i)*17 + j];
        }
        __syncthreads();
    }

    load_xtiles(sXC, sXS, n0);

#pragma unroll
    for (int i = 0; i < 4; i++) {
        float z  = acc[i] + benc[n0 + nb + i];
        float p0 = TWO_PI_F / (1.0f + expf(-z));
        int gi = (r0+row)*NN + n0 + nb + i;
        g_phi[gi]  = p0;
        float ss, cc;
        __sincosf(p0, &ss, &cc);
        g_fc[gi] = cc;
        g_fs[gi] = ss;
        sC[row*SC_STRIDE + nb + i] = cc;
        sS[row*SC_STRIDE + nb + i] = ss;
    }
    __syncthreads();
    m_tail(sC, sS, sXC, sXS, g_m[0], r0);
}

/* ================= persistent RK4 kernel: all 64 evals =================== */
__global__ void __launch_bounds__(256, 2)
k_run(EvalConsts ec) {
    extern __shared__ float sm[];
    float* sW  = sm;
    float* sXC = sm + SW_FLOATS;
    float* sXS = sXC + SX_FLOATS;
    float* sC  = sXS + SX_FLOATS;      /* cos features of eval point */
    float* sS  = sC + SC_FLOATS;       /* sin features of eval point */
    float* sP  = sS + SC_FLOATS;       /* base phi                   */
    float* sA  = sP + SC_FLOATS;       /* RK4 accumulator            */
    float* sR  = sA + SC_FLOATS;       /* GEMM partials; [0,4096)=m  */

    int n0 = blockIdx.x*CH, r0 = blockIdx.y*32;
    int tid = threadIdx.x;
    int row = tid >> 3, cf = tid & 7;
    int so  = row*SC_STRIDE + cf*4;
    int gso = (r0+row)*NN + n0 + cf*4;
    int cta = blockIdx.y*32 + blockIdx.x;

    /* ---- one-time loads: xi tiles + state ---- */
#pragma unroll
    for (int it = 0; it < 4; it++) {
        int i = tid + it*256;
        int p = i >> 3, q = (i & 7) << 2;
        CP16(su32(&sXC[p*SX_STRIDE + q]), &g_xc[p*NN + n0 + q]);
        CP16(su32(&sXS[p*SX_STRIDE + q]), &g_xs[p*NN + n0 + q]);
    }
    CP16(su32(&sC[so]), &g_fc[gso]);
    CP16(su32(&sS[so]), &g_fs[gso]);
    CP16(su32(&sP[so]), &g_phi[gso]);
    CP_COMMIT();

    for (int e = 0; e < NEV; e++) {
        int sub  = e & 3;
        int bufR = e % 3, bufW = (e + 1) % 3, bufZ = (e + 2) % 3;
        float sAnc = ec.sA[e], cAnc = ec.cA[e], cNext = ec.cN[e];

        /* prefetch m slice for this eval */
        {
            const float* gmp = &g_m[bufR][(r0+row)*PP + cf*16];
            unsigned d = su32(&sR[row*PP + cf*16]);
            CP16(d,      gmp);
            CP16(d + 16, gmp + 4);
            CP16(d + 32, gmp + 8);
            CP16(d + 48, gmp + 12);
        }
        CP_COMMIT();

        /* zero the buffer used two evals ahead */
        if (tid < 128) g_m[bufZ][cta*128 + tid] = 0.f;

        CP_WAIT(0);
        /* ---- softmax over 128 patterns (arg in [-2,2]: no max shift) ---- */
        {
            const float* mrow = &sR[row*PP + cf*16];
            float a[16];
            float ssum = 0.f;
#pragma unroll
            for (int j = 0; j < 16; j++) {
                a[j] = __expf(mrow[j] * BETA_N);
                ssum += a[j];
            }
#pragma unroll
            for (int w = 1; w < 8; w <<= 1)
                ssum += __shfl_xor_sync(0xffffffffu, ssum, w);
            float inv = 1.0f / ssum;
#pragma unroll
            for (int j = 0; j < 16; j++)
                sW[row*SW_STRIDE + cf*16 + j] = a[j] * inv;
        }
        __syncthreads();

        /* ---- coupling GEMM, tile 4 rows x 4 cols (f32x2), K-split 4 ---- */
        {
            int ks   = tid >> 6;
            int r6   = tid & 63;
            int rowg = r6 >> 3;
            int colg = r6 & 7;
            ull aC0[4], aC1[4], aS0[4], aS1[4];
#pragma unroll
            for (int i = 0; i < 4; i++) { aC0[i]=0ull; aC1[i]=0ull; aS0[i]=0ull; aS1[i]=0ull; }
            const float* wB  = &sW[(rowg*4)*SW_STRIDE + ks*32];
            const float* xcB = &sXC[(ks*32)*SX_STRIDE + colg*4];
            const float* xsB = &sXS[(ks*32)*SX_STRIDE + colg*4];
#pragma unroll 4
            for (int p = 0; p < 32; p++) {
                ulonglong2 cp = *(const ulonglong2*)&xcB[p*SX_STRIDE];
                ulonglong2 spv = *(const ulonglong2*)&xsB[p*SX_STRIDE];
#pragma unroll
                for (int i = 0; i < 4; i++) {
                    float wv = wB[i*SW_STRIDE + p];
                    ull wp = pack2(wv, wv);
                    aC0[i] = fma2(wp, cp.x,  aC0[i]);
                    aC1[i] = fma2(wp, cp.y,  aC1[i]);
                    aS0[i] = fma2(wp, spv.x, aS0[i]);
                    aS1[i] = fma2(wp, spv.y, aS1[i]);
                }
            }
            float* rr = &sR[tid*SR_STRIDE];
#pragma unroll
            for (int i = 0; i < 4; i++) {
                *(ull*)&rr[i*4]        = aC0[i];
                *(ull*)&rr[i*4 + 2]    = aC1[i];
                *(ull*)&rr[16 + i*4]   = aS0[i];
                *(ull*)&rr[16 + i*4+2] = aS1[i];
            }
        }
        __syncthreads();

        /* ---- reduce + elementwise: all 256 threads, 4 cols each ---- */
        {
            int wr = ((row >> 2) << 3) + cf;
            int ib = (row & 3) * 4;
            float wc4[4] = {0.f, 0.f, 0.f, 0.f};
            float ws4[4] = {0.f, 0.f, 0.f, 0.f};
#pragma unroll
            for (int ksr = 0; ksr < 4; ksr++) {
                const float* r = &sR[(ksr*64 + wr)*SR_STRIDE];
                float4 c4 = *(const float4*)&r[ib];
                float4 s4 = *(const float4*)&r[16 + ib];
                wc4[0] += c4.x; wc4[1] += c4.y; wc4[2] += c4.z; wc4[3] += c4.w;
                ws4[0] += s4.x; ws4[1] += s4.y; ws4[2] += s4.z; ws4[3] += s4.w;
            }

            float4 fc = *(const float4*)&sC[so];
            float4 fs = *(const float4*)&sS[so];
            float ce[4] = {fc.x, fc.y, fc.z, fc.w};
            float se[4] = {fs.x, fs.y, fs.z, fs.w};
            float kv[4];
#pragma unroll
            for (int j = 0; j < 4; j++)
                kv[j] = fmaf(se[j], wc4[j] - cAnc, ce[j] * (sAnc - ws4[j]));

            float4 p0 = *(const float4*)&sP[so];
            float ph[4] = {p0.x, p0.y, p0.z, p0.w};
            float phiN[4];
            if (sub == 0) {
                *(float4*)&sA[so] = make_float4(kv[0], kv[1], kv[2], kv[3]);
#pragma unroll
                for (int j = 0; j < 4; j++) phiN[j] = fmaf(cNext, kv[j], ph[j]);
            } else if (sub == 3) {
                float4 a0 = *(const float4*)&sA[so];
                float av[4] = {a0.x, a0.y, a0.z, a0.w};
#pragma unroll
                for (int j = 0; j < 4; j++)
                    phiN[j] = fmaf(DT/6.0f, av[j] + kv[j], ph[j]);
                *(float4*)&sP[so] = make_float4(phiN[0], phiN[1], phiN[2], phiN[3]);
            } else {
                float4 a0 = *(const float4*)&sA[so];
                float av[4] = {a0.x, a0.y, a0.z, a0.w};
#pragma unroll
                for (int j = 0; j < 4; j++) av[j] = fmaf(2.0f, kv[j], av[j]);
                *(float4*)&sA[so] = make_float4(av[0], av[1], av[2], av[3]);
#pragma unroll
                for (int j = 0; j < 4; j++) phiN[j] = fmaf(cNext, kv[j], ph[j]);
            }

            if (e < NEV-1) {
                float cn[4], sn[4];
#pragma unroll
                for (int j = 0; j < 4; j++)
                    __sincosf(phiN[j], &sn[j], &cn[j]);
                *(float4*)&sC[so] = make_float4(cn[0], cn[1], cn[2], cn[3]);
                *(float4*)&sS[so] = make_float4(sn[0], sn[1], sn[2], sn[3]);
            }
        }

        if (e < NEV-1) {
            __syncthreads();
            m_tail(sC, sS, sXC, sXS, g_m[bufW], r0);
            /* ---- grid barrier: all m atomics visible before next eval ---- */
            __syncthreads();
            if (tid == 0) {
                __threadfence();
                atomicAdd(&g_cnt[e], 1u);
                volatile unsigned* c = &g_cnt[e];
                while (*c < 256u) __nanosleep(64);
                __threadfence();
            }
            __syncthreads();
        }
    }

    /* ---- write back final phi for readout ---- */
    {
        float4 p = *(const float4*)&sP[so];
        *(float4*)&g_phi[gso] = p;
    }
}

/* ================= readout: [cos(phi), sin(phi)] @ Wout^T + b =========== */
__global__ void k_readout(const float* __restrict__ Wout,
                          const float* __restrict__ bout,
                          float* __restrict__ out) {
    __shared__ float red[256];
    int b = blockIdx.x, tid = threadIdx.x;
    float acc[COUT];
#pragma unroll
    for (int c = 0; c < COUT; c++) acc[c] = 0.f;

#pragma unroll
    for (int it = 0; it < 4; it++) {
        int n = tid + it*256;
        float phi = g_phi[b*NN + n];
        float s, c;
        sincosf(phi, &s, &c);     /* accurate: feeds output directly */
#pragma unroll
        for (int cls = 0; cls < COUT; cls++)
            acc[cls] += c*Wout[cls*(2*NN) + n] + s*Wout[cls*(2*NN) + NN + n];
    }
    for (int cls = 0; cls < COUT; cls++) {
        red[tid] = acc[cls];
        __syncthreads();
        for (int off = 128; off > 0; off >>= 1) {
            if (tid < off) red[tid] += red[tid + off];
            __syncthreads();
        }
        if (tid == 0) out[b*COUT + cls] = red[0] + bout[cls];
        __syncthreads();
    }
}

/* ================= host ================================================= */
extern "C" void kernel_launch(void* const* d_in, const int* in_sizes, int n_in,
                              void* d_out, int out_size) {
    (void)in_sizes; (void)n_in; (void)out_size;
    const float* x    = (const float*)d_in[0];
    const float* Wenc = (const float*)d_in[1];
    const float* benc = (const float*)d_in[2];
    const float* xi   = (const float*)d_in[3];
    const float* Wout = (const float*)d_in[4];
    const float* bout = (const float*)d_in[5];
    float* out = (float*)d_out;

    cudaFuncSetAttribute(k_encoder, cudaFuncAttributeMaxDynamicSharedMemorySize, SMEM_BYTES);
    cudaFuncSetAttribute(k_run,     cudaFuncAttributeMaxDynamicSharedMemorySize, SMEM_BYTES);

    EvalConsts ec;
    for (int e = 0; e < NEV; e++) {
        int step = e >> 2, sub = e & 3;
        float t0 = (float)step * DT;
        float tE = (sub == 0) ? t0 : ((sub == 3) ? t0 + DT : t0 + 0.5f*DT);
        float argf = OME * tE;
        double sa = sin((double)argf), ca = cos((double)argf);
        ec.sA[e] = (float)((double)A_ANC * sa);
        ec.cA[e] = (float)((double)A_ANC * ca);
        ec.cN[e] = (sub == 2) ? DT : 0.5f*DT;
    }

    k_init<<<512, 256>>>(xi);

    dim3 grid(NN/CH, 8);             /* 32 x 8 = 256 CTAs, all resident */
    k_encoder<<<grid, 256, SMEM_BYTES>>>(x, Wenc, benc);
    k_run<<<grid, 256, SMEM_BYTES>>>(ec);
    k_readout<<<BATCH, 256>>>(Wout, bout, out);
}

// round 10
// speedup vs baseline: 2.8367x; 1.0429x over previous
#include <cuda_runtime.h>
#include <math.h>

#define BATCH 256
#define NN    1024
#define PP    128
#define DIN   784
#define COUT  10
#define CH    32                     /* columns per CTA */
#define NEV   64                     /* RK4 evals */
#define NGRP  8                      /* row groups (blockIdx.y) */
#define GXS   32                     /* CTAs per group (blockIdx.x) */

#define TWO_PI_F 6.283185307179586f
#define DT       0.03125f            /* T/N_STEPS = 0.5/16, exact in fp32 */
#define BETA_N   (2.0f/1024.0f)
#define A_ANC    0.08f
#define OME      (TWO_PI_F*200.0f)

typedef unsigned long long ull;

__device__ __forceinline__ ull pack2(float a, float b) {
    ull r; asm("mov.b64 %0,{%1,%2};" : "=l"(r) : "f"(a), "f"(b)); return r;
}
__device__ __forceinline__ ull fma2(ull a, ull b, ull c) {
    ull d; asm("fma.rn.f32x2 %0,%1,%2,%3;" : "=l"(d) : "l"(a), "l"(b), "l"(c));
    return d;
}
__device__ __forceinline__ unsigned su32(const void* p) {
    return (unsigned)__cvta_generic_to_shared(p);
}
#define CP16(dst, src) \
    asm volatile("cp.async.cg.shared.global [%0], [%1], 16;" :: "r"(dst), "l"(src))
#define CP_COMMIT() asm volatile("cp.async.commit_group;")
#define CP_WAIT(n)  asm volatile("cp.async.wait_group %0;" :: "n"(n))

struct EvalConsts { float sA[NEV]; float cA[NEV]; float cN[NEV]; };

/* ---- device scratch (static globals; no allocation allowed) ---- */
__device__ float g_xc[PP*NN];       /* cos(xi) [p][n] */
__device__ float g_xs[PP*NN];       /* sin(xi) [p][n] */
__device__ float g_phi[BATCH*NN];   /* base state */
__device__ float g_fc[BATCH*NN];    /* cos(phi_eval) features (encoder out) */
__device__ float g_fs[BATCH*NN];    /* sin(phi_eval) features */
__device__ float g_m[3][BATCH*PP];  /* rotating overlap buffers */
__device__ unsigned g_cnt[NGRP*NEV]; /* per-(group,eval) barrier counters */

/* ---- shared layout (floats) ---- */
#define SW_STRIDE 130                /* w tile [32][130] */
#define SX_STRIDE 36                 /* xc/xs tiles [128][36] */
#define SC_STRIDE 36                 /* c/s/phi/acc tiles [32][36] */
#define SR_STRIDE 36                 /* reduction: 256 writers x 36 */
#define SW_FLOATS (32*SW_STRIDE)     /* 4160 */
#define SX_FLOATS (128*SX_STRIDE)    /* 4608 */
#define SC_FLOATS (32*SC_STRIDE)     /* 1152 */
#define SR_FLOATS (256*SR_STRIDE)    /* 9216; first 4096 alias m-prefetch */
#define SMEM_FLOATS (SW_FLOATS + 2*SX_FLOATS + 4*SC_FLOATS + SR_FLOATS)
#define SMEM_BYTES  (SMEM_FLOATS*4)  /* 108800 bytes -> 2 CTAs/SM */

/* ================= init: cos/sin of xi, zero m bufs + barrier cnt ======= */
__global__ void k_init(const float* __restrict__ xi) {
    int i = blockIdx.x*256 + threadIdx.x;
    if (i < PP*NN) {
        float v = xi[i];
        g_xc[i] = cosf(v);
        g_xs[i] = sinf(v);
    }
    if (i < BATCH*PP) { g_m[0][i] = 0.f; g_m[1][i] = 0.f; }
    if (i < NGRP*NEV) g_cnt[i] = 0u;
}

/* load xc/xs tiles [128 p][32 n] for column chunk n0 (LDG path, encoder) */
__device__ __forceinline__ void load_xtiles(float* sXC, float* sXS, int n0) {
    for (int i = threadIdx.x; i < 128*8; i += 256) {
        int p = i >> 3, q = (i & 7) << 2;
        float4 a = *(const float4*)&g_xc[p*NN + n0 + q];
        *(float4*)&sXC[p*SX_STRIDE + q] = a;
        float4 b = *(const float4*)&g_xs[p*NN + n0 + q];
        *(float4*)&sXS[p*SX_STRIDE + q] = b;
    }
}

/* partial m over this CTA's 32-col chunk, atomicAdd into mbuf. */
__device__ __forceinline__ void m_tail(const float* sC, const float* sS,
                                       const float* sXC, const float* sXS,
                                       float* mbuf, int r0) {
    int t = threadIdx.x;
    int w = t >> 5, l = t & 31;
    int ns   = l >> 4;               /* n half: 0/1 */
    int tile = w*16 + (l & 15);      /* 0..127 */
    int rowg = tile >> 5;            /* 0..3  -> rows rowg*8.. */
    int pg   = tile & 31;            /* 0..31 -> pats pg + 32*pp */
    float acc[32];
#pragma unroll
    for (int i = 0; i < 32; i++) acc[i] = 0.f;
    const float* cB  = sC  + (rowg*8)*SC_STRIDE + ns*16;
    const float* sB  = sS  + (rowg*8)*SC_STRIDE + ns*16;
    const float* xcB = sXC + pg*SX_STRIDE + ns*16;
    const float* xsB = sXS + pg*SX_STRIDE + ns*16;
#pragma unroll
    for (int nn = 0; nn < 16; nn += 4) {
        float4 cr[8], sr[8];
#pragma unroll
        for (int r = 0; r < 8; r++) {
            cr[r] = *(const float4*)&cB[r*SC_STRIDE + nn];
            sr[r] = *(const float4*)&sB[r*SC_STRIDE + nn];
        }
#pragma unroll
        for (int pp = 0; pp < 4; pp++) {
            float4 xc4 = *(const float4*)&xcB[pp*32*SX_STRIDE + nn];
            float4 xs4 = *(const float4*)&xsB[pp*32*SX_STRIDE + nn];
#pragma unroll
            for (int r = 0; r < 8; r++) {
                float v = acc[pp*8 + r];
                v = fmaf(cr[r].x, xc4.x, v); v = fmaf(sr[r].x, xs4.x, v);
                v = fmaf(cr[r].y, xc4.y, v); v = fmaf(sr[r].y, xs4.y, v);
                v = fmaf(cr[r].z, xc4.z, v); v = fmaf(sr[r].z, xs4.z, v);
                v = fmaf(cr[r].w, xc4.w, v); v = fmaf(sr[r].w, xs4.w, v);
                acc[pp*8 + r] = v;
            }
        }
    }
#pragma unroll
    for (int i = 0; i < 32; i++)
        acc[i] += __shfl_xor_sync(0xffffffffu, acc[i], 16);
    if (ns == 0) {
#pragma unroll
        for (int pp = 0; pp < 4; pp++)
#pragma unroll
            for (int r = 0; r < 8; r++)
                atomicAdd(&mbuf[(r0 + rowg*8 + r)*PP + pg + 32*pp],
                          acc[pp*8 + r]);
    }
}

/* ================= encoder: phi0 = 2pi*sigmoid(x @ Wenc^T + b), + m0 ==== */
__global__ void __launch_bounds__(256, 2)
k_encoder(const float* __restrict__ x,
          const float* __restrict__ Wenc,
          const float* __restrict__ benc) {
    extern __shared__ float sm[];
    float* sA  = sm;                 /* [32][17] staging, aliases sW region */
    float* sB  = sm + 32*17;         /* [32][17] */
    float* sXC = sm + SW_FLOATS;
    float* sXS = sXC + SX_FLOATS;
    float* sC  = sXS + SX_FLOATS;
    float* sS  = sC + SC_FLOATS;

    int n0 = blockIdx.x*CH, r0 = blockIdx.y*32;
    int tid = threadIdx.x;
    int row = tid >> 3, ng = tid & 7, nb = ng*4;

    float acc[4];
#pragma unroll
    for (int i = 0; i < 4; i++) acc[i] = 0.f;

    for (int d0 = 0; d0 < DIN; d0 += 16) {
        for (int i = tid; i < 512; i += 256) {
            int r = i >> 4, j = i & 15;
            sA[r*17 + j] = x[(r0+r)*DIN + d0 + j];
            sB[r*17 + j] = Wenc[(n0+r)*DIN + d0 + j];
        }
        __syncthreads();
#pragma unroll
        for (int j = 0; j < 16; j++) {
            float xa = sA[row*17 + j];
#pragma unroll
            for (int i = 0; i < 4; i++) acc[i] += xa * sB[(nb+i)*17 + j];
        }
        __syncthreads();
    }

    load_xtiles(sXC, sXS, n0);

#pragma unroll
    for (int i = 0; i < 4; i++) {
        float z  = acc[i] + benc[n0 + nb + i];
        float p0 = TWO_PI_F / (1.0f + expf(-z));
        int gi = (r0+row)*NN + n0 + nb + i;
        g_phi[gi]  = p0;
        float ss, cc;
        __sincosf(p0, &ss, &cc);
        g_fc[gi] = cc;
        g_fs[gi] = ss;
        sC[row*SC_STRIDE + nb + i] = cc;
        sS[row*SC_STRIDE + nb + i] = ss;
    }
    __syncthreads();
    m_tail(sC, sS, sXC, sXS, g_m[0], r0);
}

/* ================= persistent RK4 kernel: all 64 evals =================== */
__global__ void __launch_bounds__(256, 2)
k_run(EvalConsts ec) {
    extern __shared__ float sm[];
    float* sW  = sm;
    float* sXC = sm + SW_FLOATS;
    float* sXS = sXC + SX_FLOATS;
    float* sC  = sXS + SX_FLOATS;      /* cos features of eval point */
    float* sS  = sC + SC_FLOATS;       /* sin features of eval point */
    float* sP  = sS + SC_FLOATS;       /* base phi                   */
    float* sA  = sP + SC_FLOATS;       /* RK4 accumulator            */
    float* sR  = sA + SC_FLOATS;       /* GEMM partials; [0,4096)=m  */

    int n0 = blockIdx.x*CH, r0 = blockIdx.y*32;
    int tid = threadIdx.x;
    int row = tid >> 3, cf = tid & 7;
    int so  = row*SC_STRIDE + cf*4;
    int gso = (r0+row)*NN + n0 + cf*4;
    int cta = blockIdx.y*GXS + blockIdx.x;
    int grp = blockIdx.y;

    /* ---- one-time loads: xi tiles + state ---- */
#pragma unroll
    for (int it = 0; it < 4; it++) {
        int i = tid + it*256;
        int p = i >> 3, q = (i & 7) << 2;
        CP16(su32(&sXC[p*SX_STRIDE + q]), &g_xc[p*NN + n0 + q]);
        CP16(su32(&sXS[p*SX_STRIDE + q]), &g_xs[p*NN + n0 + q]);
    }
    CP16(su32(&sC[so]), &g_fc[gso]);
    CP16(su32(&sS[so]), &g_fs[gso]);
    CP16(su32(&sP[so]), &g_phi[gso]);
    CP_COMMIT();

    for (int e = 0; e < NEV; e++) {
        int sub  = e & 3;
        int bufR = e % 3, bufW = (e + 1) % 3, bufZ = (e + 2) % 3;
        float sAnc = ec.sA[e], cAnc = ec.cA[e], cNext = ec.cN[e];

        /* prefetch m slice for this eval */
        {
            const float* gmp = &g_m[bufR][(r0+row)*PP + cf*16];
            unsigned d = su32(&sR[row*PP + cf*16]);
            CP16(d,      gmp);
            CP16(d + 16, gmp + 4);
            CP16(d + 32, gmp + 8);
            CP16(d + 48, gmp + 12);
        }
        CP_COMMIT();

        /* zero this group's slice of the buffer used two evals ahead */
        if (tid < 128) g_m[bufZ][cta*128 + tid] = 0.f;

        CP_WAIT(0);
        /* ---- softmax over 128 patterns (arg in [-2,2]: no max shift) ---- */
        {
            const float* mrow = &sR[row*PP + cf*16];
            float a[16];
            float ssum = 0.f;
#pragma unroll
            for (int j = 0; j < 16; j++) {
                a[j] = __expf(mrow[j] * BETA_N);
                ssum += a[j];
            }
#pragma unroll
            for (int w = 1; w < 8; w <<= 1)
                ssum += __shfl_xor_sync(0xffffffffu, ssum, w);
            float inv = 1.0f / ssum;
#pragma unroll
            for (int j = 0; j < 16; j++)
                sW[row*SW_STRIDE + cf*16 + j] = a[j] * inv;
        }
        __syncthreads();

        /* ---- coupling GEMM, tile 4 rows x 4 cols (f32x2), K-split 4 ---- */
        {
            int ks   = tid >> 6;
            int r6   = tid & 63;
            int rowg = r6 >> 3;
            int colg = r6 & 7;
            ull aC0[4], aC1[4], aS0[4], aS1[4];
#pragma unroll
            for (int i = 0; i < 4; i++) { aC0[i]=0ull; aC1[i]=0ull; aS0[i]=0ull; aS1[i]=0ull; }
            const float* wB  = &sW[(rowg*4)*SW_STRIDE + ks*32];
            const float* xcB = &sXC[(ks*32)*SX_STRIDE + colg*4];
            const float* xsB = &sXS[(ks*32)*SX_STRIDE + colg*4];
#pragma unroll 4
            for (int p = 0; p < 32; p++) {
                ulonglong2 cp = *(const ulonglong2*)&xcB[p*SX_STRIDE];
                ulonglong2 spv = *(const ulonglong2*)&xsB[p*SX_STRIDE];
#pragma unroll
                for (int i = 0; i < 4; i++) {
                    float wv = wB[i*SW_STRIDE + p];
                    ull wp = pack2(wv, wv);
                    aC0[i] = fma2(wp, cp.x,  aC0[i]);
                    aC1[i] = fma2(wp, cp.y,  aC1[i]);
                    aS0[i] = fma2(wp, spv.x, aS0[i]);
                    aS1[i] = fma2(wp, spv.y, aS1[i]);
                }
            }
            float* rr = &sR[tid*SR_STRIDE];
#pragma unroll
            for (int i = 0; i < 4; i++) {
                *(ull*)&rr[i*4]        = aC0[i];
                *(ull*)&rr[i*4 + 2]    = aC1[i];
                *(ull*)&rr[16 + i*4]   = aS0[i];
                *(ull*)&rr[16 + i*4+2] = aS1[i];
            }
        }
        __syncthreads();

        /* ---- reduce + elementwise: all 256 threads, 4 cols each ---- */
        {
            int wr = ((row >> 2) << 3) + cf;
            int ib = (row & 3) * 4;
            float wc4[4] = {0.f, 0.f, 0.f, 0.f};
            float ws4[4] = {0.f, 0.f, 0.f, 0.f};
#pragma unroll
            for (int ksr = 0; ksr < 4; ksr++) {
                const float* r = &sR[(ksr*64 + wr)*SR_STRIDE];
                float4 c4 = *(const float4*)&r[ib];
                float4 s4 = *(const float4*)&r[16 + ib];
                wc4[0] += c4.x; wc4[1] += c4.y; wc4[2] += c4.z; wc4[3] += c4.w;
                ws4[0] += s4.x; ws4[1] += s4.y; ws4[2] += s4.z; ws4[3] += s4.w;
            }

            float4 fc = *(const float4*)&sC[so];
            float4 fs = *(const float4*)&sS[so];
            float ce[4] = {fc.x, fc.y, fc.z, fc.w};
            float se[4] = {fs.x, fs.y, fs.z, fs.w};
            float kv[4];
#pragma unroll
            for (int j = 0; j < 4; j++)
                kv[j] = fmaf(se[j], wc4[j] - cAnc, ce[j] * (sAnc - ws4[j]));

            float4 p0 = *(const float4*)&sP[so];
            float ph[4] = {p0.x, p0.y, p0.z, p0.w};
            float phiN[4];
            if (sub == 0) {
                *(float4*)&sA[so] = make_float4(kv[0], kv[1], kv[2], kv[3]);
#pragma unroll
                for (int j = 0; j < 4; j++) phiN[j] = fmaf(cNext, kv[j], ph[j]);
            } else if (sub == 3) {
                float4 a0 = *(const float4*)&sA[so];
                float av[4] = {a0.x, a0.y, a0.z, a0.w};
#pragma unroll
                for (int j = 0; j < 4; j++)
                    phiN[j] = fmaf(DT/6.0f, av[j] + kv[j], ph[j]);
                *(float4*)&sP[so] = make_float4(phiN[0], phiN[1], phiN[2], phiN[3]);
            } else {
                float4 a0 = *(const float4*)&sA[so];
                float av[4] = {a0.x, a0.y, a0.z, a0.w};
#pragma unroll
                for (int j = 0; j < 4; j++) av[j] = fmaf(2.0f, kv[j], av[j]);
                *(float4*)&sA[so] = make_float4(av[0], av[1], av[2], av[3]);
#pragma unroll
                for (int j = 0; j < 4; j++) phiN[j] = fmaf(cNext, kv[j], ph[j]);
            }

            if (e < NEV-1) {
                float cn[4], sn[4];
#pragma unroll
                for (int j = 0; j < 4; j++)
                    __sincosf(phiN[j], &sn[j], &cn[j]);
                *(float4*)&sC[so] = make_float4(cn[0], cn[1], cn[2], cn[3]);
                *(float4*)&sS[so] = make_float4(sn[0], sn[1], sn[2], sn[3]);
            }
        }

        if (e < NEV-1) {
            __syncthreads();
            m_tail(sC, sS, sXC, sXS, g_m[bufW], r0);
            /* ---- group barrier: 32 CTAs of this row group only ---- */
            __syncthreads();
            if (tid == 0) {
                __threadfence();
                atomicAdd(&g_cnt[grp*NEV + e], 1u);
                volatile unsigned* c = &g_cnt[grp*NEV + e];
                while (*c < (unsigned)GXS) { }
                __threadfence();
            }
            __syncthreads();
        }
    }

    /* ---- write back final phi for readout ---- */
    {
        float4 p = *(const float4*)&sP[so];
        *(float4*)&g_phi[gso] = p;
    }
}

/* ================= readout: [cos(phi), sin(phi)] @ Wout^T + b ===========
   One CTA per batch row; thread handles 4 n-columns; warp shfl reduce, one
   smem pass, single barrier. */
__global__ void __launch_bounds__(256)
k_readout(const float* __restrict__ Wout,
          const float* __restrict__ bout,
          float* __restrict__ out) {
    __shared__ float red[8*COUT];
    int b = blockIdx.x, tid = threadIdx.x;
    int n4 = tid*4;

    float4 p4 = *(const float4*)&g_phi[b*NN + n4];
    float ph[4] = {p4.x, p4.y, p4.z, p4.w};
    float c[4], s[4];
#pragma unroll
    for (int j = 0; j < 4; j++)
        sincosf(ph[j], &s[j], &c[j]);   /* accurate: feeds output directly */

    float acc[COUT];
#pragma unroll
    for (int cls = 0; cls < COUT; cls++) {
        float4 wcv = *(const float4*)&Wout[cls*(2*NN) + n4];
        float4 wsv = *(const float4*)&Wout[cls*(2*NN) + NN + n4];
        float a;
        a = c[0]*wcv.x + s[0]*wsv.x;
        a = fmaf(c[1], wcv.y, a); a = fmaf(s[1], wsv.y, a);
        a = fmaf(c[2], wcv.z, a); a = fmaf(s[2], wsv.z, a);
        a = fmaf(c[3], wcv.w, a); a = fmaf(s[3], wsv.w, a);
        acc[cls] = a;
    }
#pragma unroll
    for (int cls = 0; cls < COUT; cls++)
#pragma unroll
        for (int w = 16; w > 0; w >>= 1)
            acc[cls] += __shfl_xor_sync(0xffffffffu, acc[cls], w);

    int warp = tid >> 5, lane = tid & 31;
    if (lane == 0)
#pragma unroll
        for (int cls = 0; cls < COUT; cls++)
            red[warp*COUT + cls] = acc[cls];
    __syncthreads();

    if (tid < COUT) {
        float t = bout[tid];
#pragma unroll
        for (int w = 0; w < 8; w++) t += red[w*COUT + tid];
        out[b*COUT + tid] = t;
    }
}

/* ================= host ================================================= */
extern "C" void kernel_launch(void* const* d_in, const int* in_sizes, int n_in,
                              void* d_out, int out_size) {
    (void)in_sizes; (void)n_in; (void)out_size;
    const float* x    = (const float*)d_in[0];
    const float* Wenc = (const float*)d_in[1];
    const float* benc = (const float*)d_in[2];
    const float* xi   = (const float*)d_in[3];
    const float* Wout = (const float*)d_in[4];
    const float* bout = (const float*)d_in[5];
    float* out = (float*)d_out;

    cudaFuncSetAttribute(k_encoder, cudaFuncAttributeMaxDynamicSharedMemorySize, SMEM_BYTES);
    cudaFuncSetAttribute(k_run,     cudaFuncAttributeMaxDynamicSharedMemorySize, SMEM_BYTES);

    EvalConsts ec;
    for (int e = 0; e < NEV; e++) {
        int step = e >> 2, sub = e & 3;
        float t0 = (float)step * DT;
        float tE = (sub == 0) ? t0 : ((sub == 3) ? t0 + DT : t0 + 0.5f*DT);
        float argf = OME * tE;
        double sa = sin((double)argf), ca = cos((double)argf);
        ec.sA[e] = (float)((double)A_ANC * sa);
        ec.cA[e] = (float)((double)A_ANC * ca);
        ec.cN[e] = (sub == 2) ? DT : 0.5f*DT;
    }

    k_init<<<512, 256>>>(xi);

    dim3 grid(GXS, NGRP);            /* 32 x 8 = 256 CTAs, all resident */
    k_encoder<<<grid, 256, SMEM_BYTES>>>(x, Wenc, benc);
    k_run<<<grid, 256, SMEM_BYTES>>>(ec);
    k_readout<<<BATCH, 256>>>(Wout, bout, out);
}